// round 9
// baseline (speedup 1.0000x reference)
#include <cuda_runtime.h>
#include <cuda_fp16.h>
#include <math.h>
#include <stdint.h>

#define IMG_W 2048
#define IMG_H 2048
#define RANKS 128
#define KSZ   101
#define KHALF 50

// ---------------- scratch (__device__ globals; no allocation allowed) ----------------
// transposed fp16 factors, K-contiguous: [c][x][r]
__device__ __half g_Bt[3 * IMG_W * RANKS];            // from rank1 (w axis) -> GEMM B
__device__ __half g_At[3 * IMG_H * RANKS];            // from rank2 (h axis) -> GEMM A
__device__ __half g_imgh[(size_t)IMG_H * IMG_W * 4];  // fp16 interleaved [h][w][4], 32MB

__device__ __forceinline__ uint32_t smem_u32(const void* p) {
    uint32_t a;
    asm("{ .reg .u64 t; cvta.to.shared.u64 t, %1; cvt.u32.u64 %0, t; }" : "=r"(a) : "l"(p));
    return a;
}

// =====================================================================
// K1: 1D blur (SAME, zero pad) -> DIRECT transposed fp16 factor output.
// Block = one (input, c, r) row. 4 outputs/thread via float4 sliding window.
// =====================================================================
#define PAD    54
#define SROWSZ 2160
#define KWPAD  104

__global__ __launch_bounds__(256) void k_blur2(const float* __restrict__ rank1,
                                               const float* __restrict__ rank2,
                                               const float* __restrict__ sigma_p) {
    __shared__ __align__(16) float srow[SROWSZ];
    __shared__ __align__(16) float skw[KWPAD];
    const int which = blockIdx.x >= 3 * RANKS;
    const int row   = blockIdx.x - which * 3 * RANKS;   // c*128 + r
    const int c = row >> 7;
    const int r = row & 127;
    const float* in = (which ? rank2 : rank1) + (size_t)row * IMG_W;
    __half* dst = (which ? g_At : g_Bt) + (size_t)c * IMG_W * RANKS + r;
    const int tid = threadIdx.x;

    {
        float sigma = *sigma_p;
        float s   = fmaxf(sigma, 0.01f);
        float amp = 1.0f / fmaxf(sigma * 2.50662827463100050242f, 1.0f);
        for (int i = tid; i < KWPAD; i += 256) {
            float v = 0.0f;
            if (i < KSZ) {
                float n = (float)(i - KHALF);
                float t = n / s;
                v = amp * expf(-0.5f * t * t);
            }
            skw[i] = v;
        }
    }
    for (int i = tid; i < SROWSZ; i += 256) {
        int j = i - PAD;
        srow[i] = (j >= 0 && j < IMG_W) ? in[j] : 0.0f;
    }
    __syncthreads();

    #pragma unroll
    for (int grp = 0; grp < 2; grp++) {
        const int w0 = (tid + grp * 256) * 4;
        const float4* sv = (const float4*)&srow[w0 + 4];
        float a0 = 0.f, a1 = 0.f, a2 = 0.f, a3 = 0.f;
        float4 q0 = sv[0];
        #pragma unroll
        for (int t = 0; t < 26; t++) {
            float4 q1 = sv[t + 1];
            float4 kq = *(const float4*)&skw[4 * t];
            a0 = fmaf(kq.x, q0.x, a0); a1 = fmaf(kq.x, q0.y, a1);
            a2 = fmaf(kq.x, q0.z, a2); a3 = fmaf(kq.x, q0.w, a3);
            a0 = fmaf(kq.y, q0.y, a0); a1 = fmaf(kq.y, q0.z, a1);
            a2 = fmaf(kq.y, q0.w, a2); a3 = fmaf(kq.y, q1.x, a3);
            a0 = fmaf(kq.z, q0.z, a0); a1 = fmaf(kq.z, q0.w, a1);
            a2 = fmaf(kq.z, q1.x, a2); a3 = fmaf(kq.z, q1.y, a3);
            a0 = fmaf(kq.w, q0.w, a0); a1 = fmaf(kq.w, q1.x, a1);
            a2 = fmaf(kq.w, q1.y, a2); a3 = fmaf(kq.w, q1.z, a3);
            q0 = q1;
        }
        // transposed fp16 scatter: dst[x*RANKS] for x = w0..w0+3
        dst[(size_t)(w0 + 0) * RANKS] = __float2half_rn(a0);
        dst[(size_t)(w0 + 1) * RANKS] = __float2half_rn(a1);
        dst[(size_t)(w0 + 2) * RANKS] = __float2half_rn(a2);
        dst[(size_t)(w0 + 3) * RANKS] = __float2half_rn(a3);
    }
}

// =====================================================================
// K2: mma.sync fp16 GEMM (fp32 accum). Block 128x128, K=128 resident.
// 8 warps as 4(m) x 2(n); warp tile 32x64. cp.async tile loads.
// =====================================================================
#define KP 136
#define SA 0
#define SB 34816
#define SM_TOTAL 69632

__device__ __forceinline__ void ldm_x4(uint32_t* r, uint32_t addr) {
    asm volatile("ldmatrix.sync.aligned.m8n8.x4.shared.b16 {%0,%1,%2,%3}, [%4];"
                 : "=r"(r[0]), "=r"(r[1]), "=r"(r[2]), "=r"(r[3]) : "r"(addr));
}
__device__ __forceinline__ void mma_f16(float* d, const uint32_t* a, uint32_t b0, uint32_t b1) {
    asm volatile(
        "mma.sync.aligned.m16n8k16.row.col.f32.f16.f16.f32 "
        "{%0,%1,%2,%3}, {%4,%5,%6,%7}, {%8,%9}, {%0,%1,%2,%3};"
        : "+f"(d[0]), "+f"(d[1]), "+f"(d[2]), "+f"(d[3])
        : "r"(a[0]), "r"(a[1]), "r"(a[2]), "r"(a[3]), "r"(b0), "r"(b1));
}
__device__ __forceinline__ void cp16(uint32_t dst, const void* src) {
    asm volatile("cp.async.cg.shared.global [%0], [%1], 16;" :: "r"(dst), "l"(src));
}

__global__ __launch_bounds__(256, 2) void k_mma_gemm() {
    extern __shared__ char smem[];
    const uint32_t sb = smem_u32(smem);
    const int tid  = threadIdx.x;
    const int wid  = tid >> 5;
    const int lane = tid & 31;
    const int mw = wid & 3;          // 4 m-warps (32 rows)
    const int nw = wid >> 2;         // 2 n-warps (64 cols)
    const int c  = blockIdx.z;
    const int n0 = blockIdx.x * 128;
    const int m0 = blockIdx.y * 128;

    {
        const uint4* srcA = (const uint4*)(g_At + ((size_t)(c * IMG_H + m0)) * RANKS);
        const uint4* srcB = (const uint4*)(g_Bt + ((size_t)(c * IMG_W + n0)) * RANKS);
        #pragma unroll
        for (int it = 0; it < 8; it++) {           // 128 rows * 16 chunks each
            int idx = tid + it * 256;
            int row = idx >> 4, ch = idx & 15;
            uint32_t off = (uint32_t)row * (KP * 2) + ch * 16;
            cp16(sb + SA + off, srcA + (size_t)row * 16 + ch);
            cp16(sb + SB + off, srcB + (size_t)row * 16 + ch);
        }
        asm volatile("cp.async.commit_group;");
        asm volatile("cp.async.wait_group 0;");
    }
    __syncthreads();

    float d[2][8][4];
    #pragma unroll
    for (int i = 0; i < 2; i++)
        #pragma unroll
        for (int j = 0; j < 8; j++)
            #pragma unroll
            for (int r = 0; r < 4; r++) d[i][j][r] = 0.0f;

    const int a_row = (lane & 15);
    const int a_ko  = (lane >> 4) * 8;
    const int quad  = lane >> 3;
    const int b_row = ((quad >> 1) * 8) + (lane & 7);
    const int b_ko  = (quad & 1) * 8;

    #pragma unroll
    for (int ks = 0; ks < 8; ks++) {
        const int k0 = ks * 16;
        uint32_t af[2][4], bf[4][4];
        #pragma unroll
        for (int mt = 0; mt < 2; mt++)
            ldm_x4(af[mt], sb + SA +
                   ((uint32_t)(mw * 32 + mt * 16 + a_row) * KP + k0 + a_ko) * 2);
        #pragma unroll
        for (int bp = 0; bp < 4; bp++)
            ldm_x4(bf[bp], sb + SB +
                   ((uint32_t)(nw * 64 + bp * 16 + b_row) * KP + k0 + b_ko) * 2);
        #pragma unroll
        for (int mt = 0; mt < 2; mt++)
            #pragma unroll
            for (int nt = 0; nt < 8; nt++)
                mma_f16(d[mt][nt], af[mt], bf[nt >> 1][(nt & 1) * 2],
                        bf[nt >> 1][(nt & 1) * 2 + 1]);
    }

    // ---- epilogue: write fp16 channel-interleaved image ----
    const int g = lane >> 2;
    const int t = lane & 3;
    #pragma unroll
    for (int mt = 0; mt < 2; mt++) {
        #pragma unroll
        for (int nt = 0; nt < 8; nt++) {
            int m = m0 + mw * 32 + mt * 16 + g;
            int n = n0 + nw * 64 + nt * 8 + t * 2;
            __half* p0 = g_imgh + ((size_t)m * IMG_W + n) * 4 + c;
            p0[0] = __float2half_rn(d[mt][nt][0]);
            p0[4] = __float2half_rn(d[mt][nt][1]);
            __half* p1 = g_imgh + ((size_t)(m + 8) * IMG_W + n) * 4 + c;
            p1[0] = __float2half_rn(d[mt][nt][2]);
            p1[4] = __float2half_rn(d[mt][nt][3]);
        }
    }
}

// =====================================================================
// K3: bilinear grid sample; ONE 8B load per tap (pixel = 4 x fp16)
// =====================================================================
__global__ __launch_bounds__(256) void k_sample(const float* __restrict__ coord,
                                                float* __restrict__ out, int npts) {
    int p = blockIdx.x * blockDim.x + threadIdx.x;
    if (p >= npts) return;

    float2 gxy = reinterpret_cast<const float2*>(coord)[p];
    float x = (gxy.x + 1.0f) * (IMG_W * 0.5f) - 0.5f;
    float y = (gxy.y + 1.0f) * (IMG_H * 0.5f) - 0.5f;
    float x0f = floorf(x), y0f = floorf(y);
    float wx1 = x - x0f, wy1 = y - y0f;
    float wx0 = 1.0f - wx1, wy0 = 1.0f - wy1;

    int x0 = (int)x0f, y0 = (int)y0f;
    int x1 = x0 + 1,  y1 = y0 + 1;

    float vx0 = (x0 >= 0 && x0 < IMG_W) ? 1.0f : 0.0f;
    float vx1 = (x1 >= 0 && x1 < IMG_W) ? 1.0f : 0.0f;
    float vy0 = (y0 >= 0 && y0 < IMG_H) ? 1.0f : 0.0f;
    float vy1 = (y1 >= 0 && y1 < IMG_H) ? 1.0f : 0.0f;

    int cx0 = min(max(x0, 0), IMG_W - 1);
    int cx1 = min(max(x1, 0), IMG_W - 1);
    int cy0 = min(max(y0, 0), IMG_H - 1);
    int cy1 = min(max(y1, 0), IMG_H - 1);

    float w00 = wx0 * vx0 * wy0 * vy0;
    float w10 = wx1 * vx1 * wy0 * vy0;
    float w01 = wx0 * vx0 * wy1 * vy1;
    float w11 = wx1 * vx1 * wy1 * vy1;

    const uint2* img = (const uint2*)g_imgh;       // one pixel = 8B
    uint2 r00 = __ldg(&img[(size_t)cy0 * IMG_W + cx0]);
    uint2 r10 = __ldg(&img[(size_t)cy0 * IMG_W + cx1]);
    uint2 r01 = __ldg(&img[(size_t)cy1 * IMG_W + cx0]);
    uint2 r11 = __ldg(&img[(size_t)cy1 * IMG_W + cx1]);

    float2 a00 = __half22float2(*(__half2*)&r00.x);
    float2 b00 = __half22float2(*(__half2*)&r00.y);
    float2 a10 = __half22float2(*(__half2*)&r10.x);
    float2 b10 = __half22float2(*(__half2*)&r10.y);
    float2 a01 = __half22float2(*(__half2*)&r01.x);
    float2 b01 = __half22float2(*(__half2*)&r01.y);
    float2 a11 = __half22float2(*(__half2*)&r11.x);
    float2 b11 = __half22float2(*(__half2*)&r11.y);

    out[(size_t)p * 3 + 0] = w00 * a00.x + w10 * a10.x + w01 * a01.x + w11 * a11.x;
    out[(size_t)p * 3 + 1] = w00 * a00.y + w10 * a10.y + w01 * a01.y + w11 * a11.y;
    out[(size_t)p * 3 + 2] = w00 * b00.x + w10 * b10.x + w01 * b01.x + w11 * b11.x;
}

// =====================================================================
extern "C" void kernel_launch(void* const* d_in, const int* in_sizes, int n_in,
                              void* d_out, int out_size) {
    const float* rank1 = (const float*)d_in[0];
    const float* rank2 = (const float*)d_in[1];
    const float* sigma = (const float*)d_in[2];
    const float* coord = (const float*)d_in[3];
    float* out = (float*)d_out;

    const int npts = in_sizes[3] / 2;

    k_blur2<<<6 * RANKS, 256>>>(rank1, rank2, sigma);

    cudaFuncSetAttribute(k_mma_gemm, cudaFuncAttributeMaxDynamicSharedMemorySize, SM_TOTAL);
    dim3 ggrid(IMG_W / 128, IMG_H / 128, 3);
    k_mma_gemm<<<ggrid, 256, SM_TOTAL>>>();

    k_sample<<<(npts + 255) / 256, 256>>>(coord, out, npts);
    (void)n_in; (void)out_size;
}

// round 10
// speedup vs baseline: 1.0599x; 1.0599x over previous
#include <cuda_runtime.h>
#include <cuda_fp16.h>
#include <math.h>
#include <stdint.h>

#define IMG_W 2048
#define IMG_H 2048
#define RANKS 128
#define KSZ   101
#define KHALF 50

// ---------------- scratch (__device__ globals; no allocation allowed) ----------------
__device__ float g_r1b[3 * RANKS * IMG_W];            // blurred rank1 fp32 [c][r][w]
__device__ float g_r2b[3 * RANKS * IMG_H];            // blurred rank2 fp32 [c][r][h]
// transposed fp16 factors, K-contiguous: [c][x][r]
__device__ __half g_Bt[3 * IMG_W * RANKS];            // from rank1 (w axis) -> GEMM B
__device__ __half g_At[3 * IMG_H * RANKS];            // from rank2 (h axis) -> GEMM A
__device__ __half g_imgh[(size_t)IMG_H * IMG_W * 4];  // fp16 interleaved [h][w][4], 32MB

__device__ __forceinline__ uint32_t smem_u32(const void* p) {
    uint32_t a;
    asm("{ .reg .u64 t; cvta.to.shared.u64 t, %1; cvt.u32.u64 %0, t; }" : "=r"(a) : "l"(p));
    return a;
}

// =====================================================================
// K1: 1D blur (SAME, zero pad), both inputs in one launch. fp32 coalesced out.
// =====================================================================
#define PAD    54
#define SROWSZ 2160
#define KWPAD  104

__global__ __launch_bounds__(256) void k_blur2(const float* __restrict__ rank1,
                                               const float* __restrict__ rank2,
                                               const float* __restrict__ sigma_p) {
    __shared__ __align__(16) float srow[SROWSZ];
    __shared__ __align__(16) float skw[KWPAD];
    const int which = blockIdx.x >= 3 * RANKS;
    const int row   = blockIdx.x - which * 3 * RANKS;
    const float* in  = (which ? rank2 : rank1) + (size_t)row * IMG_W;
    float*       out = (which ? g_r2b : g_r1b) + (size_t)row * IMG_W;
    const int tid = threadIdx.x;

    {
        float sigma = *sigma_p;
        float s   = fmaxf(sigma, 0.01f);
        float amp = 1.0f / fmaxf(sigma * 2.50662827463100050242f, 1.0f);
        for (int i = tid; i < KWPAD; i += 256) {
            float v = 0.0f;
            if (i < KSZ) {
                float n = (float)(i - KHALF);
                float t = n / s;
                v = amp * expf(-0.5f * t * t);
            }
            skw[i] = v;
        }
    }
    for (int i = tid; i < SROWSZ; i += 256) {
        int j = i - PAD;
        srow[i] = (j >= 0 && j < IMG_W) ? in[j] : 0.0f;
    }
    __syncthreads();

    #pragma unroll
    for (int grp = 0; grp < 2; grp++) {
        const int w0 = (tid + grp * 256) * 4;
        const float4* sv = (const float4*)&srow[w0 + 4];
        float a0 = 0.f, a1 = 0.f, a2 = 0.f, a3 = 0.f;
        float4 q0 = sv[0];
        #pragma unroll
        for (int t = 0; t < 26; t++) {
            float4 q1 = sv[t + 1];
            float4 kq = *(const float4*)&skw[4 * t];
            a0 = fmaf(kq.x, q0.x, a0); a1 = fmaf(kq.x, q0.y, a1);
            a2 = fmaf(kq.x, q0.z, a2); a3 = fmaf(kq.x, q0.w, a3);
            a0 = fmaf(kq.y, q0.y, a0); a1 = fmaf(kq.y, q0.z, a1);
            a2 = fmaf(kq.y, q0.w, a2); a3 = fmaf(kq.y, q1.x, a3);
            a0 = fmaf(kq.z, q0.z, a0); a1 = fmaf(kq.z, q0.w, a1);
            a2 = fmaf(kq.z, q1.x, a2); a3 = fmaf(kq.z, q1.y, a3);
            a0 = fmaf(kq.w, q0.w, a0); a1 = fmaf(kq.w, q1.x, a1);
            a2 = fmaf(kq.w, q1.y, a2); a3 = fmaf(kq.w, q1.z, a3);
            q0 = q1;
        }
        float4 res = make_float4(a0, a1, a2, a3);
        *(float4*)&out[w0] = res;
    }
}

// =====================================================================
// K2: transpose + fp16 convert. [c][r][x] fp32 -> [c][x][r] fp16
// grid.z = 6: z%3 = channel, z/3 = which
// =====================================================================
__global__ __launch_bounds__(256) void k_split_t() {
    __shared__ float t[32][33];
    const int c     = blockIdx.z % 3;
    const int which = blockIdx.z / 3;
    const int x0 = blockIdx.x * 32;
    const int r0 = blockIdx.y * 32;
    const float* src = (which ? g_r2b : g_r1b) + (size_t)c * RANKS * IMG_W;
    __half* dst = (which ? g_At : g_Bt) + (size_t)c * IMG_W * RANKS;

    const int tx = threadIdx.x;
    const int ty = threadIdx.y;
    #pragma unroll
    for (int i = 0; i < 32; i += 8)
        t[ty + i][tx] = src[(size_t)(r0 + ty + i) * IMG_W + (x0 + tx)];
    __syncthreads();
    #pragma unroll
    for (int i = 0; i < 32; i += 8) {
        float v = t[tx][ty + i];
        dst[(size_t)(x0 + ty + i) * RANKS + (r0 + tx)] = __float2half_rn(v);
    }
}

// =====================================================================
// K3: mma.sync fp16 GEMM (fp32 accum). Block 128x128, K=128 resident.
// 8 warps as 4(m) x 2(n); warp tile 32x64. cp.async tile loads.
// =====================================================================
#define KP 136
#define SA 0
#define SB 34816
#define SM_TOTAL 69632

__device__ __forceinline__ void ldm_x4(uint32_t* r, uint32_t addr) {
    asm volatile("ldmatrix.sync.aligned.m8n8.x4.shared.b16 {%0,%1,%2,%3}, [%4];"
                 : "=r"(r[0]), "=r"(r[1]), "=r"(r[2]), "=r"(r[3]) : "r"(addr));
}
__device__ __forceinline__ void mma_f16(float* d, const uint32_t* a, uint32_t b0, uint32_t b1) {
    asm volatile(
        "mma.sync.aligned.m16n8k16.row.col.f32.f16.f16.f32 "
        "{%0,%1,%2,%3}, {%4,%5,%6,%7}, {%8,%9}, {%0,%1,%2,%3};"
        : "+f"(d[0]), "+f"(d[1]), "+f"(d[2]), "+f"(d[3])
        : "r"(a[0]), "r"(a[1]), "r"(a[2]), "r"(a[3]), "r"(b0), "r"(b1));
}
__device__ __forceinline__ void cp16(uint32_t dst, const void* src) {
    asm volatile("cp.async.cg.shared.global [%0], [%1], 16;" :: "r"(dst), "l"(src));
}

__global__ __launch_bounds__(256, 2) void k_mma_gemm() {
    extern __shared__ char smem[];
    const uint32_t sb = smem_u32(smem);
    const int tid  = threadIdx.x;
    const int wid  = tid >> 5;
    const int lane = tid & 31;
    const int mw = wid & 3;          // 4 m-warps (32 rows)
    const int nw = wid >> 2;         // 2 n-warps (64 cols)
    const int c  = blockIdx.z;
    const int n0 = blockIdx.x * 128;
    const int m0 = blockIdx.y * 128;

    {
        const uint4* srcA = (const uint4*)(g_At + ((size_t)(c * IMG_H + m0)) * RANKS);
        const uint4* srcB = (const uint4*)(g_Bt + ((size_t)(c * IMG_W + n0)) * RANKS);
        #pragma unroll
        for (int it = 0; it < 8; it++) {           // 128 rows * 16 chunks each
            int idx = tid + it * 256;
            int row = idx >> 4, ch = idx & 15;
            uint32_t off = (uint32_t)row * (KP * 2) + ch * 16;
            cp16(sb + SA + off, srcA + (size_t)row * 16 + ch);
            cp16(sb + SB + off, srcB + (size_t)row * 16 + ch);
        }
        asm volatile("cp.async.commit_group;");
        asm volatile("cp.async.wait_group 0;");
    }
    __syncthreads();

    float d[2][8][4];
    #pragma unroll
    for (int i = 0; i < 2; i++)
        #pragma unroll
        for (int j = 0; j < 8; j++)
            #pragma unroll
            for (int r = 0; r < 4; r++) d[i][j][r] = 0.0f;

    const int a_row = (lane & 15);
    const int a_ko  = (lane >> 4) * 8;
    const int quad  = lane >> 3;
    const int b_row = ((quad >> 1) * 8) + (lane & 7);
    const int b_ko  = (quad & 1) * 8;

    #pragma unroll
    for (int ks = 0; ks < 8; ks++) {
        const int k0 = ks * 16;
        uint32_t af[2][4], bf[4][4];
        #pragma unroll
        for (int mt = 0; mt < 2; mt++)
            ldm_x4(af[mt], sb + SA +
                   ((uint32_t)(mw * 32 + mt * 16 + a_row) * KP + k0 + a_ko) * 2);
        #pragma unroll
        for (int bp = 0; bp < 4; bp++)
            ldm_x4(bf[bp], sb + SB +
                   ((uint32_t)(nw * 64 + bp * 16 + b_row) * KP + k0 + b_ko) * 2);
        #pragma unroll
        for (int mt = 0; mt < 2; mt++)
            #pragma unroll
            for (int nt = 0; nt < 8; nt++)
                mma_f16(d[mt][nt], af[mt], bf[nt >> 1][(nt & 1) * 2],
                        bf[nt >> 1][(nt & 1) * 2 + 1]);
    }

    // ---- epilogue: write fp16 channel-interleaved image ----
    const int g = lane >> 2;
    const int t = lane & 3;
    #pragma unroll
    for (int mt = 0; mt < 2; mt++) {
        #pragma unroll
        for (int nt = 0; nt < 8; nt++) {
            int m = m0 + mw * 32 + mt * 16 + g;
            int n = n0 + nw * 64 + nt * 8 + t * 2;
            __half* p0 = g_imgh + ((size_t)m * IMG_W + n) * 4 + c;
            p0[0] = __float2half_rn(d[mt][nt][0]);
            p0[4] = __float2half_rn(d[mt][nt][1]);
            __half* p1 = g_imgh + ((size_t)(m + 8) * IMG_W + n) * 4 + c;
            p1[0] = __float2half_rn(d[mt][nt][2]);
            p1[4] = __float2half_rn(d[mt][nt][3]);
        }
    }
}

// =====================================================================
// K4: bilinear grid sample; ONE 8B load per tap (pixel = 4 x fp16)
// =====================================================================
__global__ __launch_bounds__(256) void k_sample(const float* __restrict__ coord,
                                                float* __restrict__ out, int npts) {
    int p = blockIdx.x * blockDim.x + threadIdx.x;
    if (p >= npts) return;

    float2 gxy = reinterpret_cast<const float2*>(coord)[p];
    float x = (gxy.x + 1.0f) * (IMG_W * 0.5f) - 0.5f;
    float y = (gxy.y + 1.0f) * (IMG_H * 0.5f) - 0.5f;
    float x0f = floorf(x), y0f = floorf(y);
    float wx1 = x - x0f, wy1 = y - y0f;
    float wx0 = 1.0f - wx1, wy0 = 1.0f - wy1;

    int x0 = (int)x0f, y0 = (int)y0f;
    int x1 = x0 + 1,  y1 = y0 + 1;

    float vx0 = (x0 >= 0 && x0 < IMG_W) ? 1.0f : 0.0f;
    float vx1 = (x1 >= 0 && x1 < IMG_W) ? 1.0f : 0.0f;
    float vy0 = (y0 >= 0 && y0 < IMG_H) ? 1.0f : 0.0f;
    float vy1 = (y1 >= 0 && y1 < IMG_H) ? 1.0f : 0.0f;

    int cx0 = min(max(x0, 0), IMG_W - 1);
    int cx1 = min(max(x1, 0), IMG_W - 1);
    int cy0 = min(max(y0, 0), IMG_H - 1);
    int cy1 = min(max(y1, 0), IMG_H - 1);

    float w00 = wx0 * vx0 * wy0 * vy0;
    float w10 = wx1 * vx1 * wy0 * vy0;
    float w01 = wx0 * vx0 * wy1 * vy1;
    float w11 = wx1 * vx1 * wy1 * vy1;

    const uint2* img = (const uint2*)g_imgh;       // one pixel = 8B
    uint2 r00 = __ldg(&img[(size_t)cy0 * IMG_W + cx0]);
    uint2 r10 = __ldg(&img[(size_t)cy0 * IMG_W + cx1]);
    uint2 r01 = __ldg(&img[(size_t)cy1 * IMG_W + cx0]);
    uint2 r11 = __ldg(&img[(size_t)cy1 * IMG_W + cx1]);

    float2 a00 = __half22float2(*(__half2*)&r00.x);
    float2 b00 = __half22float2(*(__half2*)&r00.y);
    float2 a10 = __half22float2(*(__half2*)&r10.x);
    float2 b10 = __half22float2(*(__half2*)&r10.y);
    float2 a01 = __half22float2(*(__half2*)&r01.x);
    float2 b01 = __half22float2(*(__half2*)&r01.y);
    float2 a11 = __half22float2(*(__half2*)&r11.x);
    float2 b11 = __half22float2(*(__half2*)&r11.y);

    out[(size_t)p * 3 + 0] = w00 * a00.x + w10 * a10.x + w01 * a01.x + w11 * a11.x;
    out[(size_t)p * 3 + 1] = w00 * a00.y + w10 * a10.y + w01 * a01.y + w11 * a11.y;
    out[(size_t)p * 3 + 2] = w00 * b00.x + w10 * b10.x + w01 * b01.x + w11 * b11.x;
}

// =====================================================================
extern "C" void kernel_launch(void* const* d_in, const int* in_sizes, int n_in,
                              void* d_out, int out_size) {
    const float* rank1 = (const float*)d_in[0];
    const float* rank2 = (const float*)d_in[1];
    const float* sigma = (const float*)d_in[2];
    const float* coord = (const float*)d_in[3];
    float* out = (float*)d_out;

    const int npts = in_sizes[3] / 2;

    k_blur2<<<6 * RANKS, 256>>>(rank1, rank2, sigma);

    dim3 tgrid(IMG_W / 32, RANKS / 32, 6);
    k_split_t<<<tgrid, dim3(32, 8)>>>();

    cudaFuncSetAttribute(k_mma_gemm, cudaFuncAttributeMaxDynamicSharedMemorySize, SM_TOTAL);
    dim3 ggrid(IMG_W / 128, IMG_H / 128, 3);
    k_mma_gemm<<<ggrid, 256, SM_TOTAL>>>();

    k_sample<<<(npts + 255) / 256, 256>>>(coord, out, npts);
    (void)n_in; (void)out_size;
}

// round 12
// speedup vs baseline: 1.1272x; 1.0634x over previous
#include <cuda_runtime.h>
#include <cuda_fp16.h>
#include <math.h>
#include <stdint.h>

#define IMG_W 2048
#define IMG_H 2048
#define RANKS 128
#define KSZ   101
#define KHALF 50

// ---------------- scratch (__device__ globals; no allocation allowed) ----------------
__device__ float g_r1b[3 * RANKS * IMG_W];            // blurred rank1 fp32 [c][r][w]
__device__ float g_r2b[3 * RANKS * IMG_H];            // blurred rank2 fp32 [c][r][h]
// transposed fp16 factors, K-contiguous: [c][x][r]
__device__ __half g_Bt[3 * IMG_W * RANKS];            // from rank1 (w axis) -> GEMM B
__device__ __half g_At[3 * IMG_H * RANKS];            // from rank2 (h axis) -> GEMM A
__device__ __half g_imgh[(size_t)IMG_H * IMG_W * 4];  // fp16 interleaved [h][w][4], 32MB

__device__ __forceinline__ uint32_t smem_u32(const void* p) {
    uint32_t a;
    asm("{ .reg .u64 t; cvta.to.shared.u64 t, %1; cvt.u32.u64 %0, t; }" : "=r"(a) : "l"(p));
    return a;
}

// =====================================================================
// K1: 1D blur (SAME, zero pad), both inputs in one launch.
// =====================================================================
#define PAD    54
#define SROWSZ 2160
#define KWPAD  104

__global__ __launch_bounds__(256) void k_blur2(const float* __restrict__ rank1,
                                               const float* __restrict__ rank2,
                                               const float* __restrict__ sigma_p) {
    __shared__ __align__(16) float srow[SROWSZ];
    __shared__ __align__(16) float skw[KWPAD];
    const int which = blockIdx.x >= 3 * RANKS;
    const int row   = blockIdx.x - which * 3 * RANKS;
    const float* in  = (which ? rank2 : rank1) + (size_t)row * IMG_W;
    float*       out = (which ? g_r2b : g_r1b) + (size_t)row * IMG_W;
    const int tid = threadIdx.x;

    {
        float sigma = *sigma_p;
        float s   = fmaxf(sigma, 0.01f);
        float amp = 1.0f / fmaxf(sigma * 2.50662827463100050242f, 1.0f);
        for (int i = tid; i < KWPAD; i += 256) {
            float v = 0.0f;
            if (i < KSZ) {
                float n = (float)(i - KHALF);
                float t = n / s;
                v = amp * expf(-0.5f * t * t);
            }
            skw[i] = v;
        }
    }
    for (int i = tid; i < SROWSZ; i += 256) {
        int j = i - PAD;
        srow[i] = (j >= 0 && j < IMG_W) ? in[j] : 0.0f;
    }
    __syncthreads();

    #pragma unroll
    for (int grp = 0; grp < 2; grp++) {
        const int w0 = (tid + grp * 256) * 4;
        const float4* sv = (const float4*)&srow[w0 + 4];
        float a0 = 0.f, a1 = 0.f, a2 = 0.f, a3 = 0.f;
        float4 q0 = sv[0];
        #pragma unroll
        for (int t = 0; t < 26; t++) {
            float4 q1 = sv[t + 1];
            float4 kq = *(const float4*)&skw[4 * t];
            a0 = fmaf(kq.x, q0.x, a0); a1 = fmaf(kq.x, q0.y, a1);
            a2 = fmaf(kq.x, q0.z, a2); a3 = fmaf(kq.x, q0.w, a3);
            a0 = fmaf(kq.y, q0.y, a0); a1 = fmaf(kq.y, q0.z, a1);
            a2 = fmaf(kq.y, q0.w, a2); a3 = fmaf(kq.y, q1.x, a3);
            a0 = fmaf(kq.z, q0.z, a0); a1 = fmaf(kq.z, q0.w, a1);
            a2 = fmaf(kq.z, q1.x, a2); a3 = fmaf(kq.z, q1.y, a3);
            a0 = fmaf(kq.w, q0.w, a0); a1 = fmaf(kq.w, q1.x, a1);
            a2 = fmaf(kq.w, q1.y, a2); a3 = fmaf(kq.w, q1.z, a3);
            q0 = q1;
        }
        float4 res = make_float4(a0, a1, a2, a3);
        *(float4*)&out[w0] = res;
    }
}

// =====================================================================
// K2: transpose + fp16 convert. [c][r][x] fp32 -> [c][x][r] fp16
// =====================================================================
__global__ __launch_bounds__(256) void k_split_t() {
    __shared__ float t[32][33];
    const int c     = blockIdx.z % 3;
    const int which = blockIdx.z / 3;
    const int x0 = blockIdx.x * 32;
    const int r0 = blockIdx.y * 32;
    const float* src = (which ? g_r2b : g_r1b) + (size_t)c * RANKS * IMG_W;
    __half* dst = (which ? g_At : g_Bt) + (size_t)c * IMG_W * RANKS;

    const int tx = threadIdx.x;
    const int ty = threadIdx.y;
    #pragma unroll
    for (int i = 0; i < 32; i += 8)
        t[ty + i][tx] = src[(size_t)(r0 + ty + i) * IMG_W + (x0 + tx)];
    __syncthreads();
    #pragma unroll
    for (int i = 0; i < 32; i += 8) {
        float v = t[tx][ty + i];
        dst[(size_t)(x0 + ty + i) * RANKS + (r0 + tx)] = __float2half_rn(v);
    }
}

// =====================================================================
// K3: mma.sync fp16 GEMM (fp32 accum), single pass. R8 configuration.
// Block 128(M=h) x 64(N=w), K=128 resident. 8 warps as 4(m) x 2(n).
// =====================================================================
#define KP 136
#define SA 0
#define SB 34816
#define SM_TOTAL 52224

__device__ __forceinline__ void ldm_x4(uint32_t* r, uint32_t addr) {
    asm volatile("ldmatrix.sync.aligned.m8n8.x4.shared.b16 {%0,%1,%2,%3}, [%4];"
                 : "=r"(r[0]), "=r"(r[1]), "=r"(r[2]), "=r"(r[3]) : "r"(addr));
}
__device__ __forceinline__ void mma_f16(float* d, const uint32_t* a, uint32_t b0, uint32_t b1) {
    asm volatile(
        "mma.sync.aligned.m16n8k16.row.col.f32.f16.f16.f32 "
        "{%0,%1,%2,%3}, {%4,%5,%6,%7}, {%8,%9}, {%0,%1,%2,%3};"
        : "+f"(d[0]), "+f"(d[1]), "+f"(d[2]), "+f"(d[3])
        : "r"(a[0]), "r"(a[1]), "r"(a[2]), "r"(a[3]), "r"(b0), "r"(b1));
}

__global__ __launch_bounds__(256, 3) void k_mma_gemm() {
    extern __shared__ char smem[];
    const uint32_t sb = smem_u32(smem);
    const int tid  = threadIdx.x;
    const int wid  = tid >> 5;
    const int lane = tid & 31;
    const int mw = wid & 3;
    const int nw = wid >> 2;
    const int c  = blockIdx.z;
    const int n0 = blockIdx.x * 64;
    const int m0 = blockIdx.y * 128;

    {
        const uint4* srcA = (const uint4*)(g_At + ((size_t)(c * IMG_H + m0)) * RANKS);
        const uint4* srcB = (const uint4*)(g_Bt + ((size_t)(c * IMG_W + n0)) * RANKS);
        #pragma unroll
        for (int it = 0; it < 8; it++) {           // A: 128 rows * 16 chunks
            int idx = tid + it * 256;
            int row = idx >> 4, ch = idx & 15;
            uint32_t off = (uint32_t)row * (KP * 2) + ch * 16;
            *(uint4*)(smem + SA + off) = srcA[(size_t)row * 16 + ch];
        }
        #pragma unroll
        for (int it = 0; it < 4; it++) {           // B: 64 rows * 16 chunks
            int idx = tid + it * 256;
            int row = idx >> 4, ch = idx & 15;
            uint32_t off = (uint32_t)row * (KP * 2) + ch * 16;
            *(uint4*)(smem + SB + off) = srcB[(size_t)row * 16 + ch];
        }
    }
    __syncthreads();

    float d[2][4][4];
    #pragma unroll
    for (int i = 0; i < 2; i++)
        #pragma unroll
        for (int j = 0; j < 4; j++)
            #pragma unroll
            for (int r = 0; r < 4; r++) d[i][j][r] = 0.0f;

    const int a_row = (lane & 15);
    const int a_ko  = (lane >> 4) * 8;
    const int quad  = lane >> 3;
    const int b_row = ((quad >> 1) * 8) + (lane & 7);
    const int b_ko  = (quad & 1) * 8;

    #pragma unroll
    for (int ks = 0; ks < 8; ks++) {
        const int k0 = ks * 16;
        const uint32_t aoff = ((uint32_t)(mw * 32 + a_row) * KP + k0 + a_ko) * 2;
        const uint32_t boff = ((uint32_t)(nw * 32 + b_row) * KP + k0 + b_ko) * 2;
        uint32_t af[2][4], bf[2][4];

        ldm_x4(af[0], sb + SA + aoff);
        ldm_x4(af[1], sb + SA + aoff + 16 * KP * 2);
        ldm_x4(bf[0], sb + SB + boff);
        ldm_x4(bf[1], sb + SB + boff + 16 * KP * 2);
        #pragma unroll
        for (int mt = 0; mt < 2; mt++)
            #pragma unroll
            for (int nt = 0; nt < 4; nt++)
                mma_f16(d[mt][nt], af[mt], bf[nt >> 1][(nt & 1) * 2],
                        bf[nt >> 1][(nt & 1) * 2 + 1]);
    }

    // ---- epilogue: write fp16 channel-interleaved image ----
    const int g = lane >> 2;
    const int t = lane & 3;
    #pragma unroll
    for (int mt = 0; mt < 2; mt++) {
        #pragma unroll
        for (int nt = 0; nt < 4; nt++) {
            int m = m0 + mw * 32 + mt * 16 + g;
            int n = n0 + nw * 32 + nt * 8 + t * 2;
            __half* p0 = g_imgh + ((size_t)m * IMG_W + n) * 4 + c;
            p0[0] = __float2half_rn(d[mt][nt][0]);
            p0[4] = __float2half_rn(d[mt][nt][1]);
            __half* p1 = g_imgh + ((size_t)(m + 8) * IMG_W + n) * 4 + c;
            p1[0] = __float2half_rn(d[mt][nt][2]);
            p1[4] = __float2half_rn(d[mt][nt][3]);
        }
    }
}

// =====================================================================
// K4: bilinear grid sample; one 8B load per tap; smem-staged coalesced out
// =====================================================================
__global__ __launch_bounds__(256) void k_sample(const float* __restrict__ coord,
                                                float* __restrict__ out, int npts) {
    __shared__ __align__(16) float sres[256 * 3];
    int p = blockIdx.x * 256 + threadIdx.x;
    float v0 = 0.f, v1 = 0.f, v2 = 0.f;

    if (p < npts) {
        float2 gxy = reinterpret_cast<const float2*>(coord)[p];
        float x = (gxy.x + 1.0f) * (IMG_W * 0.5f) - 0.5f;
        float y = (gxy.y + 1.0f) * (IMG_H * 0.5f) - 0.5f;
        float x0f = floorf(x), y0f = floorf(y);
        float wx1 = x - x0f, wy1 = y - y0f;
        float wx0 = 1.0f - wx1, wy0 = 1.0f - wy1;

        int x0 = (int)x0f, y0 = (int)y0f;
        int x1 = x0 + 1,  y1 = y0 + 1;

        float vx0 = (x0 >= 0 && x0 < IMG_W) ? 1.0f : 0.0f;
        float vx1 = (x1 >= 0 && x1 < IMG_W) ? 1.0f : 0.0f;
        float vy0 = (y0 >= 0 && y0 < IMG_H) ? 1.0f : 0.0f;
        float vy1 = (y1 >= 0 && y1 < IMG_H) ? 1.0f : 0.0f;

        int cx0 = min(max(x0, 0), IMG_W - 1);
        int cx1 = min(max(x1, 0), IMG_W - 1);
        int cy0 = min(max(y0, 0), IMG_H - 1);
        int cy1 = min(max(y1, 0), IMG_H - 1);

        float w00 = wx0 * vx0 * wy0 * vy0;
        float w10 = wx1 * vx1 * wy0 * vy0;
        float w01 = wx0 * vx0 * wy1 * vy1;
        float w11 = wx1 * vx1 * wy1 * vy1;

        const uint2* img = (const uint2*)g_imgh;
        uint2 r00 = __ldg(&img[(size_t)cy0 * IMG_W + cx0]);
        uint2 r10 = __ldg(&img[(size_t)cy0 * IMG_W + cx1]);
        uint2 r01 = __ldg(&img[(size_t)cy1 * IMG_W + cx0]);
        uint2 r11 = __ldg(&img[(size_t)cy1 * IMG_W + cx1]);

        float2 a00 = __half22float2(*(__half2*)&r00.x);
        float2 b00 = __half22float2(*(__half2*)&r00.y);
        float2 a10 = __half22float2(*(__half2*)&r10.x);
        float2 b10 = __half22float2(*(__half2*)&r10.y);
        float2 a01 = __half22float2(*(__half2*)&r01.x);
        float2 b01 = __half22float2(*(__half2*)&r01.y);
        float2 a11 = __half22float2(*(__half2*)&r11.x);
        float2 b11 = __half22float2(*(__half2*)&r11.y);

        v0 = w00 * a00.x + w10 * a10.x + w01 * a01.x + w11 * a11.x;
        v1 = w00 * a00.y + w10 * a10.y + w01 * a01.y + w11 * a11.y;
        v2 = w00 * b00.x + w10 * b10.x + w01 * b01.x + w11 * b11.x;
    }

    sres[threadIdx.x * 3 + 0] = v0;
    sres[threadIdx.x * 3 + 1] = v1;
    sres[threadIdx.x * 3 + 2] = v2;
    __syncthreads();

    // coalesced block output: 768 floats = 192 x float4
    size_t base = (size_t)blockIdx.x * 768;
    size_t total = (size_t)npts * 3;
    if (threadIdx.x < 192) {
        size_t o = base + threadIdx.x * 4;
        if (o + 4 <= total) {
            *(float4*)(out + o) = *(float4*)(sres + threadIdx.x * 4);
        } else {
            for (size_t k = o; k < total; k++) out[k] = sres[k - base];
        }
    }
}

// =====================================================================
extern "C" void kernel_launch(void* const* d_in, const int* in_sizes, int n_in,
                              void* d_out, int out_size) {
    const float* rank1 = (const float*)d_in[0];
    const float* rank2 = (const float*)d_in[1];
    const float* sigma = (const float*)d_in[2];
    const float* coord = (const float*)d_in[3];
    float* out = (float*)d_out;

    const int npts = in_sizes[3] / 2;

    k_blur2<<<6 * RANKS, 256>>>(rank1, rank2, sigma);

    dim3 tgrid(IMG_W / 32, RANKS / 32, 6);
    k_split_t<<<tgrid, dim3(32, 8)>>>();

    cudaFuncSetAttribute(k_mma_gemm, cudaFuncAttributeMaxDynamicSharedMemorySize, SM_TOTAL);
    dim3 ggrid(IMG_W / 64, IMG_H / 128, 3);
    k_mma_gemm<<<ggrid, 256, SM_TOTAL>>>();

    k_sample<<<(npts + 255) / 256, 256>>>(coord, out, npts);
    (void)n_in; (void)out_size;
}

// round 13
// speedup vs baseline: 1.1738x; 1.0413x over previous
#include <cuda_runtime.h>
#include <cuda_fp16.h>
#include <math.h>
#include <stdint.h>

#define IMG_W 2048
#define IMG_H 2048
#define RANKS 128
#define KSZ   101
#define KHALF 50

// ---------------- scratch (__device__ globals; no allocation allowed) ----------------
// fp16 blurred factors in natural [c][r][x] layout (K-major for the GEMM)
__device__ __half g_Bh[3 * RANKS * IMG_W];            // from rank1 (w axis) -> GEMM B
__device__ __half g_Ah[3 * RANKS * IMG_H];            // from rank2 (h axis) -> GEMM A
__device__ __half g_imgh[(size_t)IMG_H * IMG_W * 4];  // fp16 interleaved [h][w][4], 32MB

__device__ __forceinline__ uint32_t smem_u32(const void* p) {
    uint32_t a;
    asm("{ .reg .u64 t; cvta.to.shared.u64 t, %1; cvt.u32.u64 %0, t; }" : "=r"(a) : "l"(p));
    return a;
}

// =====================================================================
// K1: 1D blur (SAME, zero pad), both inputs in one launch.
// Output: fp16, coalesced, natural [c][r][x] layout.
// =====================================================================
#define PAD    54
#define SROWSZ 2160
#define KWPAD  104

__global__ __launch_bounds__(256) void k_blur2(const float* __restrict__ rank1,
                                               const float* __restrict__ rank2,
                                               const float* __restrict__ sigma_p) {
    __shared__ __align__(16) float srow[SROWSZ];
    __shared__ __align__(16) float skw[KWPAD];
    const int which = blockIdx.x >= 3 * RANKS;
    const int row   = blockIdx.x - which * 3 * RANKS;
    const float* in = (which ? rank2 : rank1) + (size_t)row * IMG_W;
    __half*     out = (which ? g_Ah : g_Bh) + (size_t)row * IMG_W;
    const int tid = threadIdx.x;

    {
        float sigma = *sigma_p;
        float s   = fmaxf(sigma, 0.01f);
        float amp = 1.0f / fmaxf(sigma * 2.50662827463100050242f, 1.0f);
        for (int i = tid; i < KWPAD; i += 256) {
            float v = 0.0f;
            if (i < KSZ) {
                float n = (float)(i - KHALF);
                float t = n / s;
                v = amp * expf(-0.5f * t * t);
            }
            skw[i] = v;
        }
    }
    for (int i = tid; i < SROWSZ; i += 256) {
        int j = i - PAD;
        srow[i] = (j >= 0 && j < IMG_W) ? in[j] : 0.0f;
    }
    __syncthreads();

    #pragma unroll
    for (int grp = 0; grp < 2; grp++) {
        const int w0 = (tid + grp * 256) * 4;
        const float4* sv = (const float4*)&srow[w0 + 4];
        float a0 = 0.f, a1 = 0.f, a2 = 0.f, a3 = 0.f;
        float4 q0 = sv[0];
        #pragma unroll
        for (int t = 0; t < 26; t++) {
            float4 q1 = sv[t + 1];
            float4 kq = *(const float4*)&skw[4 * t];
            a0 = fmaf(kq.x, q0.x, a0); a1 = fmaf(kq.x, q0.y, a1);
            a2 = fmaf(kq.x, q0.z, a2); a3 = fmaf(kq.x, q0.w, a3);
            a0 = fmaf(kq.y, q0.y, a0); a1 = fmaf(kq.y, q0.z, a1);
            a2 = fmaf(kq.y, q0.w, a2); a3 = fmaf(kq.y, q1.x, a3);
            a0 = fmaf(kq.z, q0.z, a0); a1 = fmaf(kq.z, q0.w, a1);
            a2 = fmaf(kq.z, q1.x, a2); a3 = fmaf(kq.z, q1.y, a3);
            a0 = fmaf(kq.w, q0.w, a0); a1 = fmaf(kq.w, q1.x, a1);
            a2 = fmaf(kq.w, q1.y, a2); a3 = fmaf(kq.w, q1.z, a3);
            q0 = q1;
        }
        __half2 h01 = __floats2half2_rn(a0, a1);
        __half2 h23 = __floats2half2_rn(a2, a3);
        uint2 pack = make_uint2(*(uint32_t*)&h01, *(uint32_t*)&h23);
        *(uint2*)&out[w0] = pack;
    }
}

// =====================================================================
// K2: mma.sync fp16 GEMM (fp32 accum). K-major smem tiles + ldmatrix.trans.
// Block 128(M=h) x 64(N=w), K=128 resident. 8 warps as 4(m) x 2(n).
// =====================================================================
#define MP 136                       // A smem col stride (halves)
#define NP 72                        // B smem col stride (halves)
#define SA 0
#define SB (128 * MP * 2)            // 34816
#define SM_TOTAL (SB + 128 * NP * 2) // 53248

__device__ __forceinline__ void ldm_x4_t(uint32_t* r, uint32_t addr) {
    asm volatile("ldmatrix.sync.aligned.m8n8.x4.trans.shared.b16 {%0,%1,%2,%3}, [%4];"
                 : "=r"(r[0]), "=r"(r[1]), "=r"(r[2]), "=r"(r[3]) : "r"(addr));
}
__device__ __forceinline__ void mma_f16(float* d, const uint32_t* a, uint32_t b0, uint32_t b1) {
    asm volatile(
        "mma.sync.aligned.m16n8k16.row.col.f32.f16.f16.f32 "
        "{%0,%1,%2,%3}, {%4,%5,%6,%7}, {%8,%9}, {%0,%1,%2,%3};"
        : "+f"(d[0]), "+f"(d[1]), "+f"(d[2]), "+f"(d[3])
        : "r"(a[0]), "r"(a[1]), "r"(a[2]), "r"(a[3]), "r"(b0), "r"(b1));
}

__global__ __launch_bounds__(256, 3) void k_mma_gemm() {
    extern __shared__ char smem[];
    const uint32_t sb = smem_u32(smem);
    const int tid  = threadIdx.x;
    const int wid  = tid >> 5;
    const int lane = tid & 31;
    const int mw = wid & 3;
    const int nw = wid >> 2;
    const int c  = blockIdx.z;
    const int n0 = blockIdx.x * 64;
    const int m0 = blockIdx.y * 128;

    // ---- load K-major tiles: A[k][m] (128x128), B[k][n] (128x64) ----
    {
        const __half* srcA = g_Ah + (size_t)c * RANKS * IMG_H + m0;  // row r: + r*IMG_H
        const __half* srcB = g_Bh + (size_t)c * RANKS * IMG_W + n0;
        #pragma unroll
        for (int it = 0; it < 8; it++) {           // A: 128 rows * 16 chunks(16B)
            int idx = tid + it * 256;
            int r = idx >> 4, ch = idx & 15;
            const uint4 v = *(const uint4*)(srcA + (size_t)r * IMG_H + ch * 8);
            *(uint4*)(smem + SA + (uint32_t)r * (MP * 2) + ch * 16) = v;
        }
        #pragma unroll
        for (int it = 0; it < 4; it++) {           // B: 128 rows * 8 chunks(16B)
            int idx = tid + it * 256;
            int r = idx >> 3, ch = idx & 7;
            const uint4 v = *(const uint4*)(srcB + (size_t)r * IMG_W + ch * 8);
            *(uint4*)(smem + SB + (uint32_t)r * (NP * 2) + ch * 16) = v;
        }
    }
    __syncthreads();

    float d[2][4][4];
    #pragma unroll
    for (int i = 0; i < 2; i++)
        #pragma unroll
        for (int j = 0; j < 4; j++)
            #pragma unroll
            for (int r = 0; r < 4; r++) d[i][j][r] = 0.0f;

    const int quad = lane >> 3;
    const int l7   = lane & 7;
    // A (trans): k_row = k0 + (quad>>1)*8 + l7 ; m_col = base_m + (quad&1)*8
    const int a_kq = (quad >> 1) * 8 + l7;
    const int a_mq = (quad & 1) * 8;
    // B (trans): k_row = k0 + (quad&1)*8 + l7 ; n_col = base_n + (quad>>1)*8
    const int b_kq = (quad & 1) * 8 + l7;
    const int b_nq = (quad >> 1) * 8;

    #pragma unroll
    for (int ks = 0; ks < 8; ks++) {
        const int k0 = ks * 16;
        uint32_t af[2][4], bf[2][4];
        #pragma unroll
        for (int mt = 0; mt < 2; mt++)
            ldm_x4_t(af[mt], sb + SA +
                     ((uint32_t)(k0 + a_kq) * MP + mw * 32 + mt * 16 + a_mq) * 2);
        #pragma unroll
        for (int bp = 0; bp < 2; bp++)
            ldm_x4_t(bf[bp], sb + SB +
                     ((uint32_t)(k0 + b_kq) * NP + nw * 32 + bp * 16 + b_nq) * 2);
        #pragma unroll
        for (int mt = 0; mt < 2; mt++)
            #pragma unroll
            for (int nt = 0; nt < 4; nt++)
                mma_f16(d[mt][nt], af[mt], bf[nt >> 1][(nt & 1) * 2],
                        bf[nt >> 1][(nt & 1) * 2 + 1]);
    }

    // ---- epilogue: write fp16 channel-interleaved image ----
    const int g = lane >> 2;
    const int t = lane & 3;
    #pragma unroll
    for (int mt = 0; mt < 2; mt++) {
        #pragma unroll
        for (int nt = 0; nt < 4; nt++) {
            int m = m0 + mw * 32 + mt * 16 + g;
            int n = n0 + nw * 32 + nt * 8 + t * 2;
            __half* p0 = g_imgh + ((size_t)m * IMG_W + n) * 4 + c;
            p0[0] = __float2half_rn(d[mt][nt][0]);
            p0[4] = __float2half_rn(d[mt][nt][1]);
            __half* p1 = g_imgh + ((size_t)(m + 8) * IMG_W + n) * 4 + c;
            p1[0] = __float2half_rn(d[mt][nt][2]);
            p1[4] = __float2half_rn(d[mt][nt][3]);
        }
    }
}

// =====================================================================
// K3: bilinear grid sample; one 8B load per tap; smem-staged coalesced out
// =====================================================================
__global__ __launch_bounds__(256) void k_sample(const float* __restrict__ coord,
                                                float* __restrict__ out, int npts) {
    __shared__ __align__(16) float sres[256 * 3];
    int p = blockIdx.x * 256 + threadIdx.x;
    float v0 = 0.f, v1 = 0.f, v2 = 0.f;

    if (p < npts) {
        float2 gxy = reinterpret_cast<const float2*>(coord)[p];
        float x = (gxy.x + 1.0f) * (IMG_W * 0.5f) - 0.5f;
        float y = (gxy.y + 1.0f) * (IMG_H * 0.5f) - 0.5f;
        float x0f = floorf(x), y0f = floorf(y);
        float wx1 = x - x0f, wy1 = y - y0f;
        float wx0 = 1.0f - wx1, wy0 = 1.0f - wy1;

        int x0 = (int)x0f, y0 = (int)y0f;
        int x1 = x0 + 1,  y1 = y0 + 1;

        float vx0 = (x0 >= 0 && x0 < IMG_W) ? 1.0f : 0.0f;
        float vx1 = (x1 >= 0 && x1 < IMG_W) ? 1.0f : 0.0f;
        float vy0 = (y0 >= 0 && y0 < IMG_H) ? 1.0f : 0.0f;
        float vy1 = (y1 >= 0 && y1 < IMG_H) ? 1.0f : 0.0f;

        int cx0 = min(max(x0, 0), IMG_W - 1);
        int cx1 = min(max(x1, 0), IMG_W - 1);
        int cy0 = min(max(y0, 0), IMG_H - 1);
        int cy1 = min(max(y1, 0), IMG_H - 1);

        float w00 = wx0 * vx0 * wy0 * vy0;
        float w10 = wx1 * vx1 * wy0 * vy0;
        float w01 = wx0 * vx0 * wy1 * vy1;
        float w11 = wx1 * vx1 * wy1 * vy1;

        const uint2* img = (const uint2*)g_imgh;
        uint2 r00 = __ldg(&img[(size_t)cy0 * IMG_W + cx0]);
        uint2 r10 = __ldg(&img[(size_t)cy0 * IMG_W + cx1]);
        uint2 r01 = __ldg(&img[(size_t)cy1 * IMG_W + cx0]);
        uint2 r11 = __ldg(&img[(size_t)cy1 * IMG_W + cx1]);

        float2 a00 = __half22float2(*(__half2*)&r00.x);
        float2 b00 = __half22float2(*(__half2*)&r00.y);
        float2 a10 = __half22float2(*(__half2*)&r10.x);
        float2 b10 = __half22float2(*(__half2*)&r10.y);
        float2 a01 = __half22float2(*(__half2*)&r01.x);
        float2 b01 = __half22float2(*(__half2*)&r01.y);
        float2 a11 = __half22float2(*(__half2*)&r11.x);
        float2 b11 = __half22float2(*(__half2*)&r11.y);

        v0 = w00 * a00.x + w10 * a10.x + w01 * a01.x + w11 * a11.x;
        v1 = w00 * a00.y + w10 * a10.y + w01 * a01.y + w11 * a11.y;
        v2 = w00 * b00.x + w10 * b10.x + w01 * b01.x + w11 * b11.x;
    }

    sres[threadIdx.x * 3 + 0] = v0;
    sres[threadIdx.x * 3 + 1] = v1;
    sres[threadIdx.x * 3 + 2] = v2;
    __syncthreads();

    size_t base = (size_t)blockIdx.x * 768;
    size_t total = (size_t)npts * 3;
    if (threadIdx.x < 192) {
        size_t o = base + threadIdx.x * 4;
        if (o + 4 <= total) {
            *(float4*)(out + o) = *(float4*)(sres + threadIdx.x * 4);
        } else {
            for (size_t k = o; k < total; k++) out[k] = sres[k - base];
        }
    }
}

// =====================================================================
extern "C" void kernel_launch(void* const* d_in, const int* in_sizes, int n_in,
                              void* d_out, int out_size) {
    const float* rank1 = (const float*)d_in[0];
    const float* rank2 = (const float*)d_in[1];
    const float* sigma = (const float*)d_in[2];
    const float* coord = (const float*)d_in[3];
    float* out = (float*)d_out;

    const int npts = in_sizes[3] / 2;

    k_blur2<<<6 * RANKS, 256>>>(rank1, rank2, sigma);

    cudaFuncSetAttribute(k_mma_gemm, cudaFuncAttributeMaxDynamicSharedMemorySize, SM_TOTAL);
    dim3 ggrid(IMG_W / 64, IMG_H / 128, 3);
    k_mma_gemm<<<ggrid, 256, SM_TOTAL>>>();

    k_sample<<<(npts + 255) / 256, 256>>>(coord, out, npts);
    (void)n_in; (void)out_size;
}

// round 14
// speedup vs baseline: 1.2186x; 1.0382x over previous
#include <cuda_runtime.h>
#include <cuda_fp16.h>
#include <math.h>
#include <stdint.h>

#define IMG_W 2048
#define IMG_H 2048
#define RANKS 128
#define KSZ   101
#define KHALF 50

// ---------------- scratch (__device__ globals; no allocation allowed) ----------------
// fp16 blurred factors in natural [c][r][x] layout (K-major for the GEMM)
__device__ __half g_Bh[3 * RANKS * IMG_W];            // from rank1 (w axis) -> GEMM B
__device__ __half g_Ah[3 * RANKS * IMG_H];            // from rank2 (h axis) -> GEMM A
__device__ __half g_imgh[(size_t)IMG_H * IMG_W * 4];  // fp16 interleaved [h][w][4], 32MB

__device__ __forceinline__ uint32_t smem_u32(const void* p) {
    uint32_t a;
    asm("{ .reg .u64 t; cvta.to.shared.u64 t, %1; cvt.u32.u64 %0, t; }" : "=r"(a) : "l"(p));
    return a;
}

// =====================================================================
// K1: 1D blur (SAME, zero pad), both inputs in one launch.
// Output: fp16, coalesced, natural [c][r][x] layout.
// Reg-capped + partial unroll so occupancy (not per-thread ILP) hides LDS latency.
// =====================================================================
#define PAD    54
#define SROWSZ 2160
#define KWPAD  104

__global__ __launch_bounds__(256, 4) void k_blur2(const float* __restrict__ rank1,
                                                  const float* __restrict__ rank2,
                                                  const float* __restrict__ sigma_p) {
    __shared__ __align__(16) float srow[SROWSZ];
    __shared__ __align__(16) float skw[KWPAD];
    const int which = blockIdx.x >= 3 * RANKS;
    const int row   = blockIdx.x - which * 3 * RANKS;
    const float* in = (which ? rank2 : rank1) + (size_t)row * IMG_W;
    __half*     out = (which ? g_Ah : g_Bh) + (size_t)row * IMG_W;
    const int tid = threadIdx.x;

    {
        float sigma = *sigma_p;
        float s   = fmaxf(sigma, 0.01f);
        float amp = 1.0f / fmaxf(sigma * 2.50662827463100050242f, 1.0f);
        for (int i = tid; i < KWPAD; i += 256) {
            float v = 0.0f;
            if (i < KSZ) {
                float n = (float)(i - KHALF);
                float t = n / s;
                v = amp * expf(-0.5f * t * t);
            }
            skw[i] = v;
        }
    }
    for (int i = tid; i < SROWSZ; i += 256) {
        int j = i - PAD;
        srow[i] = (j >= 0 && j < IMG_W) ? in[j] : 0.0f;
    }
    __syncthreads();

    #pragma unroll 1
    for (int grp = 0; grp < 2; grp++) {
        const int w0 = (tid + grp * 256) * 4;
        const float4* sv = (const float4*)&srow[w0 + 4];
        float a0 = 0.f, a1 = 0.f, a2 = 0.f, a3 = 0.f;
        float4 q0 = sv[0];
        #pragma unroll 4
        for (int t = 0; t < 26; t++) {
            float4 q1 = sv[t + 1];
            float4 kq = *(const float4*)&skw[4 * t];
            a0 = fmaf(kq.x, q0.x, a0); a1 = fmaf(kq.x, q0.y, a1);
            a2 = fmaf(kq.x, q0.z, a2); a3 = fmaf(kq.x, q0.w, a3);
            a0 = fmaf(kq.y, q0.y, a0); a1 = fmaf(kq.y, q0.z, a1);
            a2 = fmaf(kq.y, q0.w, a2); a3 = fmaf(kq.y, q1.x, a3);
            a0 = fmaf(kq.z, q0.z, a0); a1 = fmaf(kq.z, q0.w, a1);
            a2 = fmaf(kq.z, q1.x, a2); a3 = fmaf(kq.z, q1.y, a3);
            a0 = fmaf(kq.w, q0.w, a0); a1 = fmaf(kq.w, q1.x, a1);
            a2 = fmaf(kq.w, q1.y, a2); a3 = fmaf(kq.w, q1.z, a3);
            q0 = q1;
        }
        __half2 h01 = __floats2half2_rn(a0, a1);
        __half2 h23 = __floats2half2_rn(a2, a3);
        uint2 pack = make_uint2(*(uint32_t*)&h01, *(uint32_t*)&h23);
        *(uint2*)&out[w0] = pack;
    }
}

// =====================================================================
// K2: mma.sync fp16 GEMM (fp32 accum). K-major smem tiles + ldmatrix.trans.
// Block 128(M=h) x 64(N=w), K=128 resident. 8 warps as 4(m) x 2(n).
// =====================================================================
#define MP 136                       // A smem col stride (halves)
#define NP 72                        // B smem col stride (halves)
#define SA 0
#define SB (128 * MP * 2)            // 34816
#define SM_TOTAL (SB + 128 * NP * 2) // 53248

__device__ __forceinline__ void ldm_x4_t(uint32_t* r, uint32_t addr) {
    asm volatile("ldmatrix.sync.aligned.m8n8.x4.trans.shared.b16 {%0,%1,%2,%3}, [%4];"
                 : "=r"(r[0]), "=r"(r[1]), "=r"(r[2]), "=r"(r[3]) : "r"(addr));
}
__device__ __forceinline__ void mma_f16(float* d, const uint32_t* a, uint32_t b0, uint32_t b1) {
    asm volatile(
        "mma.sync.aligned.m16n8k16.row.col.f32.f16.f16.f32 "
        "{%0,%1,%2,%3}, {%4,%5,%6,%7}, {%8,%9}, {%0,%1,%2,%3};"
        : "+f"(d[0]), "+f"(d[1]), "+f"(d[2]), "+f"(d[3])
        : "r"(a[0]), "r"(a[1]), "r"(a[2]), "r"(a[3]), "r"(b0), "r"(b1));
}

__global__ __launch_bounds__(256, 3) void k_mma_gemm() {
    extern __shared__ char smem[];
    const uint32_t sb = smem_u32(smem);
    const int tid  = threadIdx.x;
    const int wid  = tid >> 5;
    const int lane = tid & 31;
    const int mw = wid & 3;
    const int nw = wid >> 2;
    const int c  = blockIdx.z;
    const int n0 = blockIdx.x * 64;
    const int m0 = blockIdx.y * 128;

    // ---- load K-major tiles: A[k][m] (128x128), B[k][n] (128x64) ----
    {
        const __half* srcA = g_Ah + (size_t)c * RANKS * IMG_H + m0;
        const __half* srcB = g_Bh + (size_t)c * RANKS * IMG_W + n0;
        #pragma unroll
        for (int it = 0; it < 8; it++) {           // A: 128 rows * 16 chunks(16B)
            int idx = tid + it * 256;
            int r = idx >> 4, ch = idx & 15;
            const uint4 v = *(const uint4*)(srcA + (size_t)r * IMG_H + ch * 8);
            *(uint4*)(smem + SA + (uint32_t)r * (MP * 2) + ch * 16) = v;
        }
        #pragma unroll
        for (int it = 0; it < 4; it++) {           // B: 128 rows * 8 chunks(16B)
            int idx = tid + it * 256;
            int r = idx >> 3, ch = idx & 7;
            const uint4 v = *(const uint4*)(srcB + (size_t)r * IMG_W + ch * 8);
            *(uint4*)(smem + SB + (uint32_t)r * (NP * 2) + ch * 16) = v;
        }
    }
    __syncthreads();

    float d[2][4][4];
    #pragma unroll
    for (int i = 0; i < 2; i++)
        #pragma unroll
        for (int j = 0; j < 4; j++)
            #pragma unroll
            for (int r = 0; r < 4; r++) d[i][j][r] = 0.0f;

    const int quad = lane >> 3;
    const int l7   = lane & 7;
    const int a_kq = (quad >> 1) * 8 + l7;
    const int a_mq = (quad & 1) * 8;
    const int b_kq = (quad & 1) * 8 + l7;
    const int b_nq = (quad >> 1) * 8;

    #pragma unroll
    for (int ks = 0; ks < 8; ks++) {
        const int k0 = ks * 16;
        uint32_t af[2][4], bf[2][4];
        #pragma unroll
        for (int mt = 0; mt < 2; mt++)
            ldm_x4_t(af[mt], sb + SA +
                     ((uint32_t)(k0 + a_kq) * MP + mw * 32 + mt * 16 + a_mq) * 2);
        #pragma unroll
        for (int bp = 0; bp < 2; bp++)
            ldm_x4_t(bf[bp], sb + SB +
                     ((uint32_t)(k0 + b_kq) * NP + nw * 32 + bp * 16 + b_nq) * 2);
        #pragma unroll
        for (int mt = 0; mt < 2; mt++)
            #pragma unroll
            for (int nt = 0; nt < 4; nt++)
                mma_f16(d[mt][nt], af[mt], bf[nt >> 1][(nt & 1) * 2],
                        bf[nt >> 1][(nt & 1) * 2 + 1]);
    }

    // ---- epilogue: write fp16 channel-interleaved image ----
    const int g = lane >> 2;
    const int t = lane & 3;
    #pragma unroll
    for (int mt = 0; mt < 2; mt++) {
        #pragma unroll
        for (int nt = 0; nt < 4; nt++) {
            int m = m0 + mw * 32 + mt * 16 + g;
            int n = n0 + nw * 32 + nt * 8 + t * 2;
            __half* p0 = g_imgh + ((size_t)m * IMG_W + n) * 4 + c;
            p0[0] = __float2half_rn(d[mt][nt][0]);
            p0[4] = __float2half_rn(d[mt][nt][1]);
            __half* p1 = g_imgh + ((size_t)(m + 8) * IMG_W + n) * 4 + c;
            p1[0] = __float2half_rn(d[mt][nt][2]);
            p1[4] = __float2half_rn(d[mt][nt][3]);
        }
    }
}

// =====================================================================
// K3: bilinear grid sample; one 8B load per tap; smem-staged coalesced out
// =====================================================================
__global__ __launch_bounds__(256) void k_sample(const float* __restrict__ coord,
                                                float* __restrict__ out, int npts) {
    __shared__ __align__(16) float sres[256 * 3];
    int p = blockIdx.x * 256 + threadIdx.x;
    float v0 = 0.f, v1 = 0.f, v2 = 0.f;

    if (p < npts) {
        float2 gxy = reinterpret_cast<const float2*>(coord)[p];
        float x = (gxy.x + 1.0f) * (IMG_W * 0.5f) - 0.5f;
        float y = (gxy.y + 1.0f) * (IMG_H * 0.5f) - 0.5f;
        float x0f = floorf(x), y0f = floorf(y);
        float wx1 = x - x0f, wy1 = y - y0f;
        float wx0 = 1.0f - wx1, wy0 = 1.0f - wy1;

        int x0 = (int)x0f, y0 = (int)y0f;
        int x1 = x0 + 1,  y1 = y0 + 1;

        float vx0 = (x0 >= 0 && x0 < IMG_W) ? 1.0f : 0.0f;
        float vx1 = (x1 >= 0 && x1 < IMG_W) ? 1.0f : 0.0f;
        float vy0 = (y0 >= 0 && y0 < IMG_H) ? 1.0f : 0.0f;
        float vy1 = (y1 >= 0 && y1 < IMG_H) ? 1.0f : 0.0f;

        int cx0 = min(max(x0, 0), IMG_W - 1);
        int cx1 = min(max(x1, 0), IMG_W - 1);
        int cy0 = min(max(y0, 0), IMG_H - 1);
        int cy1 = min(max(y1, 0), IMG_H - 1);

        float w00 = wx0 * vx0 * wy0 * vy0;
        float w10 = wx1 * vx1 * wy0 * vy0;
        float w01 = wx0 * vx0 * wy1 * vy1;
        float w11 = wx1 * vx1 * wy1 * vy1;

        const uint2* img = (const uint2*)g_imgh;
        uint2 r00 = __ldg(&img[(size_t)cy0 * IMG_W + cx0]);
        uint2 r10 = __ldg(&img[(size_t)cy0 * IMG_W + cx1]);
        uint2 r01 = __ldg(&img[(size_t)cy1 * IMG_W + cx0]);
        uint2 r11 = __ldg(&img[(size_t)cy1 * IMG_W + cx1]);

        float2 a00 = __half22float2(*(__half2*)&r00.x);
        float2 b00 = __half22float2(*(__half2*)&r00.y);
        float2 a10 = __half22float2(*(__half2*)&r10.x);
        float2 b10 = __half22float2(*(__half2*)&r10.y);
        float2 a01 = __half22float2(*(__half2*)&r01.x);
        float2 b01 = __half22float2(*(__half2*)&r01.y);
        float2 a11 = __half22float2(*(__half2*)&r11.x);
        float2 b11 = __half22float2(*(__half2*)&r11.y);

        v0 = w00 * a00.x + w10 * a10.x + w01 * a01.x + w11 * a11.x;
        v1 = w00 * a00.y + w10 * a10.y + w01 * a01.y + w11 * a11.y;
        v2 = w00 * b00.x + w10 * b10.x + w01 * b01.x + w11 * b11.x;
    }

    sres[threadIdx.x * 3 + 0] = v0;
    sres[threadIdx.x * 3 + 1] = v1;
    sres[threadIdx.x * 3 + 2] = v2;
    __syncthreads();

    size_t base = (size_t)blockIdx.x * 768;
    size_t total = (size_t)npts * 3;
    if (threadIdx.x < 192) {
        size_t o = base + threadIdx.x * 4;
        if (o + 4 <= total) {
            *(float4*)(out + o) = *(float4*)(sres + threadIdx.x * 4);
        } else {
            for (size_t k = o; k < total; k++) out[k] = sres[k - base];
        }
    }
}

// =====================================================================
extern "C" void kernel_launch(void* const* d_in, const int* in_sizes, int n_in,
                              void* d_out, int out_size) {
    const float* rank1 = (const float*)d_in[0];
    const float* rank2 = (const float*)d_in[1];
    const float* sigma = (const float*)d_in[2];
    const float* coord = (const float*)d_in[3];
    float* out = (float*)d_out;

    const int npts = in_sizes[3] / 2;

    k_blur2<<<6 * RANKS, 256>>>(rank1, rank2, sigma);

    cudaFuncSetAttribute(k_mma_gemm, cudaFuncAttributeMaxDynamicSharedMemorySize, SM_TOTAL);
    dim3 ggrid(IMG_W / 64, IMG_H / 128, 3);
    k_mma_gemm<<<ggrid, 256, SM_TOTAL>>>();

    k_sample<<<(npts + 255) / 256, 256>>>(coord, out, npts);
    (void)n_in; (void)out_size;
}

// round 15
// speedup vs baseline: 1.2516x; 1.0271x over previous
#include <cuda_runtime.h>
#include <cuda_fp16.h>
#include <math.h>
#include <stdint.h>

#define IMG_W 2048
#define IMG_H 2048
#define RANKS 128
#define KSZ   101
#define KHALF 50

// ---------------- scratch (__device__ globals; no allocation allowed) ----------------
// fp16 blurred factors in natural [c][r][x] layout (K-major for the GEMM)
__device__ __half g_Bh[3 * RANKS * IMG_W];            // from rank1 (w axis) -> GEMM B
__device__ __half g_Ah[3 * RANKS * IMG_H];            // from rank2 (h axis) -> GEMM A
__device__ __half g_imgh[(size_t)IMG_H * IMG_W * 4];  // fp16 interleaved [h][w][4], 32MB

__device__ __forceinline__ uint32_t smem_u32(const void* p) {
    uint32_t a;
    asm("{ .reg .u64 t; cvta.to.shared.u64 t, %1; cvt.u32.u64 %0, t; }" : "=r"(a) : "l"(p));
    return a;
}

// =====================================================================
// K1: 1D blur (SAME, zero pad), both inputs in one launch.
// Output: fp16, coalesced, natural [c][r][x] layout.
// occ-6 cap -> 888-CTA capacity -> single wave for the 768-CTA grid.
// =====================================================================
#define PAD    54
#define SROWSZ 2160
#define KWPAD  104

__global__ __launch_bounds__(256, 6) void k_blur2(const float* __restrict__ rank1,
                                                  const float* __restrict__ rank2,
                                                  const float* __restrict__ sigma_p) {
    __shared__ __align__(16) float srow[SROWSZ];
    __shared__ __align__(16) float skw[KWPAD];
    const int which = blockIdx.x >= 3 * RANKS;
    const int row   = blockIdx.x - which * 3 * RANKS;
    const float* in = (which ? rank2 : rank1) + (size_t)row * IMG_W;
    __half*     out = (which ? g_Ah : g_Bh) + (size_t)row * IMG_W;
    const int tid = threadIdx.x;

    {
        float sigma = *sigma_p;
        float s   = fmaxf(sigma, 0.01f);
        float amp = 1.0f / fmaxf(sigma * 2.50662827463100050242f, 1.0f);
        for (int i = tid; i < KWPAD; i += 256) {
            float v = 0.0f;
            if (i < KSZ) {
                float n = (float)(i - KHALF);
                float t = n / s;
                v = amp * expf(-0.5f * t * t);
            }
            skw[i] = v;
        }
    }
    for (int i = tid; i < SROWSZ; i += 256) {
        int j = i - PAD;
        srow[i] = (j >= 0 && j < IMG_W) ? in[j] : 0.0f;
    }
    __syncthreads();

    #pragma unroll 1
    for (int grp = 0; grp < 2; grp++) {
        const int w0 = (tid + grp * 256) * 4;
        const float4* sv = (const float4*)&srow[w0 + 4];
        float a0 = 0.f, a1 = 0.f, a2 = 0.f, a3 = 0.f;
        float4 q0 = sv[0];
        #pragma unroll 4
        for (int t = 0; t < 26; t++) {
            float4 q1 = sv[t + 1];
            float4 kq = *(const float4*)&skw[4 * t];
            a0 = fmaf(kq.x, q0.x, a0); a1 = fmaf(kq.x, q0.y, a1);
            a2 = fmaf(kq.x, q0.z, a2); a3 = fmaf(kq.x, q0.w, a3);
            a0 = fmaf(kq.y, q0.y, a0); a1 = fmaf(kq.y, q0.z, a1);
            a2 = fmaf(kq.y, q0.w, a2); a3 = fmaf(kq.y, q1.x, a3);
            a0 = fmaf(kq.z, q0.z, a0); a1 = fmaf(kq.z, q0.w, a1);
            a2 = fmaf(kq.z, q1.x, a2); a3 = fmaf(kq.z, q1.y, a3);
            a0 = fmaf(kq.w, q0.w, a0); a1 = fmaf(kq.w, q1.x, a1);
            a2 = fmaf(kq.w, q1.y, a2); a3 = fmaf(kq.w, q1.z, a3);
            q0 = q1;
        }
        __half2 h01 = __floats2half2_rn(a0, a1);
        __half2 h23 = __floats2half2_rn(a2, a3);
        uint2 pack = make_uint2(*(uint32_t*)&h01, *(uint32_t*)&h23);
        *(uint2*)&out[w0] = pack;
    }
}

// =====================================================================
// K2: mma.sync fp16 GEMM (fp32 accum). K-major smem tiles + ldmatrix.trans.
// Block 128(M=h) x 64(N=w), K=128 resident. 8 warps as 4(m) x 2(n).
// =====================================================================
#define MP 136                       // A smem col stride (halves)
#define NP 72                        // B smem col stride (halves)
#define SA 0
#define SB (128 * MP * 2)            // 34816
#define SM_TOTAL (SB + 128 * NP * 2) // 53248

__device__ __forceinline__ void ldm_x4_t(uint32_t* r, uint32_t addr) {
    asm volatile("ldmatrix.sync.aligned.m8n8.x4.trans.shared.b16 {%0,%1,%2,%3}, [%4];"
                 : "=r"(r[0]), "=r"(r[1]), "=r"(r[2]), "=r"(r[3]) : "r"(addr));
}
__device__ __forceinline__ void mma_f16(float* d, const uint32_t* a, uint32_t b0, uint32_t b1) {
    asm volatile(
        "mma.sync.aligned.m16n8k16.row.col.f32.f16.f16.f32 "
        "{%0,%1,%2,%3}, {%4,%5,%6,%7}, {%8,%9}, {%0,%1,%2,%3};"
        : "+f"(d[0]), "+f"(d[1]), "+f"(d[2]), "+f"(d[3])
        : "r"(a[0]), "r"(a[1]), "r"(a[2]), "r"(a[3]), "r"(b0), "r"(b1));
}

__global__ __launch_bounds__(256, 3) void k_mma_gemm() {
    extern __shared__ char smem[];
    const uint32_t sb = smem_u32(smem);
    const int tid  = threadIdx.x;
    const int wid  = tid >> 5;
    const int lane = tid & 31;
    const int mw = wid & 3;
    const int nw = wid >> 2;
    const int c  = blockIdx.z;
    const int n0 = blockIdx.x * 64;
    const int m0 = blockIdx.y * 128;

    // ---- load K-major tiles: A[k][m] (128x128), B[k][n] (128x64) ----
    {
        const __half* srcA = g_Ah + (size_t)c * RANKS * IMG_H + m0;
        const __half* srcB = g_Bh + (size_t)c * RANKS * IMG_W + n0;
        #pragma unroll
        for (int it = 0; it < 8; it++) {           // A: 128 rows * 16 chunks(16B)
            int idx = tid + it * 256;
            int r = idx >> 4, ch = idx & 15;
            const uint4 v = *(const uint4*)(srcA + (size_t)r * IMG_H + ch * 8);
            *(uint4*)(smem + SA + (uint32_t)r * (MP * 2) + ch * 16) = v;
        }
        #pragma unroll
        for (int it = 0; it < 4; it++) {           // B: 128 rows * 8 chunks(16B)
            int idx = tid + it * 256;
            int r = idx >> 3, ch = idx & 7;
            const uint4 v = *(const uint4*)(srcB + (size_t)r * IMG_W + ch * 8);
            *(uint4*)(smem + SB + (uint32_t)r * (NP * 2) + ch * 16) = v;
        }
    }
    __syncthreads();

    float d[2][4][4];
    #pragma unroll
    for (int i = 0; i < 2; i++)
        #pragma unroll
        for (int j = 0; j < 4; j++)
            #pragma unroll
            for (int r = 0; r < 4; r++) d[i][j][r] = 0.0f;

    const int quad = lane >> 3;
    const int l7   = lane & 7;
    const int a_kq = (quad >> 1) * 8 + l7;
    const int a_mq = (quad & 1) * 8;
    const int b_kq = (quad & 1) * 8 + l7;
    const int b_nq = (quad >> 1) * 8;

    #pragma unroll
    for (int ks = 0; ks < 8; ks++) {
        const int k0 = ks * 16;
        uint32_t af[2][4], bf[2][4];
        #pragma unroll
        for (int mt = 0; mt < 2; mt++)
            ldm_x4_t(af[mt], sb + SA +
                     ((uint32_t)(k0 + a_kq) * MP + mw * 32 + mt * 16 + a_mq) * 2);
        #pragma unroll
        for (int bp = 0; bp < 2; bp++)
            ldm_x4_t(bf[bp], sb + SB +
                     ((uint32_t)(k0 + b_kq) * NP + nw * 32 + bp * 16 + b_nq) * 2);
        #pragma unroll
        for (int mt = 0; mt < 2; mt++)
            #pragma unroll
            for (int nt = 0; nt < 4; nt++)
                mma_f16(d[mt][nt], af[mt], bf[nt >> 1][(nt & 1) * 2],
                        bf[nt >> 1][(nt & 1) * 2 + 1]);
    }

    // ---- epilogue: write fp16 channel-interleaved image ----
    const int g = lane >> 2;
    const int t = lane & 3;
    #pragma unroll
    for (int mt = 0; mt < 2; mt++) {
        #pragma unroll
        for (int nt = 0; nt < 4; nt++) {
            int m = m0 + mw * 32 + mt * 16 + g;
            int n = n0 + nw * 32 + nt * 8 + t * 2;
            __half* p0 = g_imgh + ((size_t)m * IMG_W + n) * 4 + c;
            p0[0] = __float2half_rn(d[mt][nt][0]);
            p0[4] = __float2half_rn(d[mt][nt][1]);
            __half* p1 = g_imgh + ((size_t)(m + 8) * IMG_W + n) * 4 + c;
            p1[0] = __float2half_rn(d[mt][nt][2]);
            p1[4] = __float2half_rn(d[mt][nt][3]);
        }
    }
}

// =====================================================================
// K3: bilinear grid sample; one 8B load per tap; smem-staged coalesced out
// =====================================================================
__global__ __launch_bounds__(256) void k_sample(const float* __restrict__ coord,
                                                float* __restrict__ out, int npts) {
    __shared__ __align__(16) float sres[256 * 3];
    int p = blockIdx.x * 256 + threadIdx.x;
    float v0 = 0.f, v1 = 0.f, v2 = 0.f;

    if (p < npts) {
        float2 gxy = reinterpret_cast<const float2*>(coord)[p];
        float x = (gxy.x + 1.0f) * (IMG_W * 0.5f) - 0.5f;
        float y = (gxy.y + 1.0f) * (IMG_H * 0.5f) - 0.5f;
        float x0f = floorf(x), y0f = floorf(y);
        float wx1 = x - x0f, wy1 = y - y0f;
        float wx0 = 1.0f - wx1, wy0 = 1.0f - wy1;

        int x0 = (int)x0f, y0 = (int)y0f;
        int x1 = x0 + 1,  y1 = y0 + 1;

        float vx0 = (x0 >= 0 && x0 < IMG_W) ? 1.0f : 0.0f;
        float vx1 = (x1 >= 0 && x1 < IMG_W) ? 1.0f : 0.0f;
        float vy0 = (y0 >= 0 && y0 < IMG_H) ? 1.0f : 0.0f;
        float vy1 = (y1 >= 0 && y1 < IMG_H) ? 1.0f : 0.0f;

        int cx0 = min(max(x0, 0), IMG_W - 1);
        int cx1 = min(max(x1, 0), IMG_W - 1);
        int cy0 = min(max(y0, 0), IMG_H - 1);
        int cy1 = min(max(y1, 0), IMG_H - 1);

        float w00 = wx0 * vx0 * wy0 * vy0;
        float w10 = wx1 * vx1 * wy0 * vy0;
        float w01 = wx0 * vx0 * wy1 * vy1;
        float w11 = wx1 * vx1 * wy1 * vy1;

        const uint2* img = (const uint2*)g_imgh;
        uint2 r00 = __ldg(&img[(size_t)cy0 * IMG_W + cx0]);
        uint2 r10 = __ldg(&img[(size_t)cy0 * IMG_W + cx1]);
        uint2 r01 = __ldg(&img[(size_t)cy1 * IMG_W + cx0]);
        uint2 r11 = __ldg(&img[(size_t)cy1 * IMG_W + cx1]);

        float2 a00 = __half22float2(*(__half2*)&r00.x);
        float2 b00 = __half22float2(*(__half2*)&r00.y);
        float2 a10 = __half22float2(*(__half2*)&r10.x);
        float2 b10 = __half22float2(*(__half2*)&r10.y);
        float2 a01 = __half22float2(*(__half2*)&r01.x);
        float2 b01 = __half22float2(*(__half2*)&r01.y);
        float2 a11 = __half22float2(*(__half2*)&r11.x);
        float2 b11 = __half22float2(*(__half2*)&r11.y);

        v0 = w00 * a00.x + w10 * a10.x + w01 * a01.x + w11 * a11.x;
        v1 = w00 * a00.y + w10 * a10.y + w01 * a01.y + w11 * a11.y;
        v2 = w00 * b00.x + w10 * b10.x + w01 * b01.x + w11 * b11.x;
    }

    sres[threadIdx.x * 3 + 0] = v0;
    sres[threadIdx.x * 3 + 1] = v1;
    sres[threadIdx.x * 3 + 2] = v2;
    __syncthreads();

    size_t base = (size_t)blockIdx.x * 768;
    size_t total = (size_t)npts * 3;
    if (threadIdx.x < 192) {
        size_t o = base + threadIdx.x * 4;
        if (o + 4 <= total) {
            *(float4*)(out + o) = *(float4*)(sres + threadIdx.x * 4);
        } else {
            for (size_t k = o; k < total; k++) out[k] = sres[k - base];
        }
    }
}

// =====================================================================
extern "C" void kernel_launch(void* const* d_in, const int* in_sizes, int n_in,
                              void* d_out, int out_size) {
    const float* rank1 = (const float*)d_in[0];
    const float* rank2 = (const float*)d_in[1];
    const float* sigma = (const float*)d_in[2];
    const float* coord = (const float*)d_in[3];
    float* out = (float*)d_out;

    const int npts = in_sizes[3] / 2;

    k_blur2<<<6 * RANKS, 256>>>(rank1, rank2, sigma);

    cudaFuncSetAttribute(k_mma_gemm, cudaFuncAttributeMaxDynamicSharedMemorySize, SM_TOTAL);
    dim3 ggrid(IMG_W / 64, IMG_H / 128, 3);
    k_mma_gemm<<<ggrid, 256, SM_TOTAL>>>();

    k_sample<<<(npts + 255) / 256, 256>>>(coord, out, npts);
    (void)n_in; (void)out_size;
}

// round 16
// speedup vs baseline: 1.5541x; 1.2417x over previous
#include <cuda_runtime.h>
#include <cuda_fp16.h>
#include <math.h>
#include <stdint.h>

#define IMG_W 2048
#define IMG_H 2048
#define RANKS 128
#define KSZ   101
#define KHALF 50

// ---------------- scratch (__device__ globals; no allocation allowed) ----------------
// fp16 blurred factors in natural [c][r][x] layout (K-major for the GEMM)
__device__ __half g_Bh[3 * RANKS * IMG_W];            // from rank1 (w axis) -> GEMM B
__device__ __half g_Ah[3 * RANKS * IMG_H];            // from rank2 (h axis) -> GEMM A
__device__ __half g_imgh[(size_t)IMG_H * IMG_W * 4];  // fp16 interleaved [h][w][4], 32MB

__device__ __forceinline__ uint32_t smem_u32(const void* p) {
    uint32_t a;
    asm("{ .reg .u64 t; cvta.to.shared.u64 t, %1; cvt.u32.u64 %0, t; }" : "=r"(a) : "l"(p));
    return a;
}

// =====================================================================
// K1: 1D blur (SAME, zero pad), both inputs in one launch.
// =====================================================================
#define PAD    54
#define SROWSZ 2160
#define KWPAD  104

__global__ __launch_bounds__(256, 6) void k_blur2(const float* __restrict__ rank1,
                                                  const float* __restrict__ rank2,
                                                  const float* __restrict__ sigma_p) {
    __shared__ __align__(16) float srow[SROWSZ];
    __shared__ __align__(16) float skw[KWPAD];
    const int which = blockIdx.x >= 3 * RANKS;
    const int row   = blockIdx.x - which * 3 * RANKS;
    const float* in = (which ? rank2 : rank1) + (size_t)row * IMG_W;
    __half*     out = (which ? g_Ah : g_Bh) + (size_t)row * IMG_W;
    const int tid = threadIdx.x;

    {
        float sigma = *sigma_p;
        float s   = fmaxf(sigma, 0.01f);
        float amp = 1.0f / fmaxf(sigma * 2.50662827463100050242f, 1.0f);
        for (int i = tid; i < KWPAD; i += 256) {
            float v = 0.0f;
            if (i < KSZ) {
                float n = (float)(i - KHALF);
                float t = n / s;
                v = amp * expf(-0.5f * t * t);
            }
            skw[i] = v;
        }
    }
    for (int i = tid; i < SROWSZ; i += 256) {
        int j = i - PAD;
        srow[i] = (j >= 0 && j < IMG_W) ? in[j] : 0.0f;
    }
    __syncthreads();

    #pragma unroll 1
    for (int grp = 0; grp < 2; grp++) {
        const int w0 = (tid + grp * 256) * 4;
        const float4* sv = (const float4*)&srow[w0 + 4];
        float a0 = 0.f, a1 = 0.f, a2 = 0.f, a3 = 0.f;
        float4 q0 = sv[0];
        #pragma unroll 4
        for (int t = 0; t < 26; t++) {
            float4 q1 = sv[t + 1];
            float4 kq = *(const float4*)&skw[4 * t];
            a0 = fmaf(kq.x, q0.x, a0); a1 = fmaf(kq.x, q0.y, a1);
            a2 = fmaf(kq.x, q0.z, a2); a3 = fmaf(kq.x, q0.w, a3);
            a0 = fmaf(kq.y, q0.y, a0); a1 = fmaf(kq.y, q0.z, a1);
            a2 = fmaf(kq.y, q0.w, a2); a3 = fmaf(kq.y, q1.x, a3);
            a0 = fmaf(kq.z, q0.z, a0); a1 = fmaf(kq.z, q0.w, a1);
            a2 = fmaf(kq.z, q1.x, a2); a3 = fmaf(kq.z, q1.y, a3);
            a0 = fmaf(kq.w, q0.w, a0); a1 = fmaf(kq.w, q1.x, a1);
            a2 = fmaf(kq.w, q1.y, a2); a3 = fmaf(kq.w, q1.z, a3);
            q0 = q1;
        }
        __half2 h01 = __floats2half2_rn(a0, a1);
        __half2 h23 = __floats2half2_rn(a2, a3);
        uint2 pack = make_uint2(*(uint32_t*)&h01, *(uint32_t*)&h23);
        *(uint2*)&out[w0] = pack;
    }
}

// =====================================================================
// K2: fused 3-channel mma.sync fp16 GEMM. Tile 64x64 pixels, K=128 resident.
// Per channel: load K-major tiles, ldmatrix.trans + mma, stage fp16 to smem.
// Final: coalesced uint4 writes of interleaved [h][w][4] pixels.
// =====================================================================
#define TP 72                        // tile smem col stride (halves)
#define SA 0
#define SB (128 * TP * 2)            // 18432
#define SS (2 * 128 * TP * 2)        // 36864 staging: 64 rows * 32 pairs * 16B
#define SM_TOTAL (SS + 64 * 32 * 16) // 69632

__device__ __forceinline__ void ldm_x4_t(uint32_t* r, uint32_t addr) {
    asm volatile("ldmatrix.sync.aligned.m8n8.x4.trans.shared.b16 {%0,%1,%2,%3}, [%4];"
                 : "=r"(r[0]), "=r"(r[1]), "=r"(r[2]), "=r"(r[3]) : "r"(addr));
}
__device__ __forceinline__ void mma_f16(float* d, const uint32_t* a, uint32_t b0, uint32_t b1) {
    asm volatile(
        "mma.sync.aligned.m16n8k16.row.col.f32.f16.f16.f32 "
        "{%0,%1,%2,%3}, {%4,%5,%6,%7}, {%8,%9}, {%0,%1,%2,%3};"
        : "+f"(d[0]), "+f"(d[1]), "+f"(d[2]), "+f"(d[3])
        : "r"(a[0]), "r"(a[1]), "r"(a[2]), "r"(a[3]), "r"(b0), "r"(b1));
}

__global__ __launch_bounds__(256, 3) void k_mma_gemm() {
    extern __shared__ char smem[];
    const uint32_t sb = smem_u32(smem);
    const int tid  = threadIdx.x;
    const int wid  = tid >> 5;
    const int lane = tid & 31;
    const int mw = wid & 1;          // 2 m-warps (32 rows)
    const int nw = wid >> 1;         // 4 n-warps (16 cols)
    const int n0 = blockIdx.x * 64;
    const int m0 = blockIdx.y * 64;

    const int quad = lane >> 3;
    const int l7   = lane & 7;
    const int a_kq = (quad >> 1) * 8 + l7;
    const int a_mq = (quad & 1) * 8;
    const int b_kq = (quad & 1) * 8 + l7;
    const int b_nq = (quad >> 1) * 8;
    const int g = lane >> 2;
    const int t = lane & 3;

    #pragma unroll 1
    for (int c = 0; c < 3; c++) {
        // ---- load K-major tiles: A[k][m0:m0+64], B[k][n0:n0+64] ----
        {
            const __half* srcA = g_Ah + (size_t)c * RANKS * IMG_H + m0;
            const __half* srcB = g_Bh + (size_t)c * RANKS * IMG_W + n0;
            #pragma unroll
            for (int it = 0; it < 4; it++) {       // 128 rows * 8 chunks(16B)
                int idx = tid + it * 256;
                int r = idx >> 3, ch = idx & 7;
                uint32_t off = (uint32_t)r * (TP * 2) + ch * 16;
                *(uint4*)(smem + SA + off) = *(const uint4*)(srcA + (size_t)r * IMG_H + ch * 8);
                *(uint4*)(smem + SB + off) = *(const uint4*)(srcB + (size_t)r * IMG_W + ch * 8);
            }
        }
        __syncthreads();

        float d[2][2][4];
        #pragma unroll
        for (int i = 0; i < 2; i++)
            #pragma unroll
            for (int j = 0; j < 2; j++)
                #pragma unroll
                for (int r = 0; r < 4; r++) d[i][j][r] = 0.0f;

        #pragma unroll
        for (int ks = 0; ks < 8; ks++) {
            const int k0 = ks * 16;
            uint32_t af[2][4], bf[4];
            #pragma unroll
            for (int mt = 0; mt < 2; mt++)
                ldm_x4_t(af[mt], sb + SA +
                         ((uint32_t)(k0 + a_kq) * TP + mw * 32 + mt * 16 + a_mq) * 2);
            ldm_x4_t(bf, sb + SB +
                     ((uint32_t)(k0 + b_kq) * TP + nw * 16 + b_nq) * 2);
            #pragma unroll
            for (int mt = 0; mt < 2; mt++)
                #pragma unroll
                for (int nt = 0; nt < 2; nt++)
                    mma_f16(d[mt][nt], af[mt], bf[nt * 2], bf[nt * 2 + 1]);
        }

        // ---- stage to swizzled pixel buffer: pixel (m,n) pair p=n>>1, pp=p^(m&7)
        //      byte = SS + (m*32 + pp)*16 + (n&1)*8 + c*2
        #pragma unroll
        for (int mt = 0; mt < 2; mt++) {
            #pragma unroll
            for (int nt = 0; nt < 2; nt++) {
                int pbase = nw * 8 + nt * 4 + t;   // pixel pair index 0..31
                int mlo = mw * 32 + mt * 16 + g;
                int mhi = mlo + 8;
                uint32_t alo = SS + ((uint32_t)mlo * 32 + (pbase ^ (mlo & 7))) * 16 + c * 2;
                uint32_t ahi = SS + ((uint32_t)mhi * 32 + (pbase ^ (mhi & 7))) * 16 + c * 2;
                *(__half*)(smem + alo)     = __float2half_rn(d[mt][nt][0]);
                *(__half*)(smem + alo + 8) = __float2half_rn(d[mt][nt][1]);
                *(__half*)(smem + ahi)     = __float2half_rn(d[mt][nt][2]);
                *(__half*)(smem + ahi + 8) = __float2half_rn(d[mt][nt][3]);
            }
        }
        __syncthreads();   // staging done; tiles safe to overwrite next channel
    }

    // ---- coalesced output: 64 rows * 32 pixel-pairs * 16B ----
    #pragma unroll
    for (int it = 0; it < 8; it++) {
        int idx = tid + it * 256;
        int m = idx >> 5, q = idx & 31;
        uint4 v = *(uint4*)(smem + SS + ((uint32_t)m * 32 + (q ^ (m & 7))) * 16);
        *(uint4*)((char*)g_imgh + ((size_t)(m0 + m) * IMG_W + n0 + q * 2) * 8) = v;
    }
}

// =====================================================================
// K3: bilinear grid sample; one 8B load per tap; smem-staged coalesced out
// =====================================================================
__global__ __launch_bounds__(256) void k_sample(const float* __restrict__ coord,
                                                float* __restrict__ out, int npts) {
    __shared__ __align__(16) float sres[256 * 3];
    int p = blockIdx.x * 256 + threadIdx.x;
    float v0 = 0.f, v1 = 0.f, v2 = 0.f;

    if (p < npts) {
        float2 gxy = reinterpret_cast<const float2*>(coord)[p];
        float x = (gxy.x + 1.0f) * (IMG_W * 0.5f) - 0.5f;
        float y = (gxy.y + 1.0f) * (IMG_H * 0.5f) - 0.5f;
        float x0f = floorf(x), y0f = floorf(y);
        float wx1 = x - x0f, wy1 = y - y0f;
        float wx0 = 1.0f - wx1, wy0 = 1.0f - wy1;

        int x0 = (int)x0f, y0 = (int)y0f;
        int x1 = x0 + 1,  y1 = y0 + 1;

        float vx0 = (x0 >= 0 && x0 < IMG_W) ? 1.0f : 0.0f;
        float vx1 = (x1 >= 0 && x1 < IMG_W) ? 1.0f : 0.0f;
        float vy0 = (y0 >= 0 && y0 < IMG_H) ? 1.0f : 0.0f;
        float vy1 = (y1 >= 0 && y1 < IMG_H) ? 1.0f : 0.0f;

        int cx0 = min(max(x0, 0), IMG_W - 1);
        int cx1 = min(max(x1, 0), IMG_W - 1);
        int cy0 = min(max(y0, 0), IMG_H - 1);
        int cy1 = min(max(y1, 0), IMG_H - 1);

        float w00 = wx0 * vx0 * wy0 * vy0;
        float w10 = wx1 * vx1 * wy0 * vy0;
        float w01 = wx0 * vx0 * wy1 * vy1;
        float w11 = wx1 * vx1 * wy1 * vy1;

        const uint2* img = (const uint2*)g_imgh;
        uint2 r00 = __ldg(&img[(size_t)cy0 * IMG_W + cx0]);
        uint2 r10 = __ldg(&img[(size_t)cy0 * IMG_W + cx1]);
        uint2 r01 = __ldg(&img[(size_t)cy1 * IMG_W + cx0]);
        uint2 r11 = __ldg(&img[(size_t)cy1 * IMG_W + cx1]);

        float2 a00 = __half22float2(*(__half2*)&r00.x);
        float2 b00 = __half22float2(*(__half2*)&r00.y);
        float2 a10 = __half22float2(*(__half2*)&r10.x);
        float2 b10 = __half22float2(*(__half2*)&r10.y);
        float2 a01 = __half22float2(*(__half2*)&r01.x);
        float2 b01 = __half22float2(*(__half2*)&r01.y);
        float2 a11 = __half22float2(*(__half2*)&r11.x);
        float2 b11 = __half22float2(*(__half2*)&r11.y);

        v0 = w00 * a00.x + w10 * a10.x + w01 * a01.x + w11 * a11.x;
        v1 = w00 * a00.y + w10 * a10.y + w01 * a01.y + w11 * a11.y;
        v2 = w00 * b00.x + w10 * b10.x + w01 * b01.x + w11 * b11.x;
    }

    sres[threadIdx.x * 3 + 0] = v0;
    sres[threadIdx.x * 3 + 1] = v1;
    sres[threadIdx.x * 3 + 2] = v2;
    __syncthreads();

    size_t base = (size_t)blockIdx.x * 768;
    size_t total = (size_t)npts * 3;
    if (threadIdx.x < 192) {
        size_t o = base + threadIdx.x * 4;
        if (o + 4 <= total) {
            *(float4*)(out + o) = *(float4*)(sres + threadIdx.x * 4);
        } else {
            for (size_t k = o; k < total; k++) out[k] = sres[k - base];
        }
    }
}

// =====================================================================
extern "C" void kernel_launch(void* const* d_in, const int* in_sizes, int n_in,
                              void* d_out, int out_size) {
    const float* rank1 = (const float*)d_in[0];
    const float* rank2 = (const float*)d_in[1];
    const float* sigma = (const float*)d_in[2];
    const float* coord = (const float*)d_in[3];
    float* out = (float*)d_out;

    const int npts = in_sizes[3] / 2;

    k_blur2<<<6 * RANKS, 256>>>(rank1, rank2, sigma);

    cudaFuncSetAttribute(k_mma_gemm, cudaFuncAttributeMaxDynamicSharedMemorySize, SM_TOTAL);
    dim3 ggrid(IMG_W / 64, IMG_H / 64);
    k_mma_gemm<<<ggrid, 256, SM_TOTAL>>>();

    k_sample<<<(npts + 255) / 256, 256>>>(coord, out, npts);
    (void)n_in; (void)out_size;
}